// round 1
// baseline (speedup 1.0000x reference)
#include <cuda_runtime.h>

// ---------------------------------------------------------------------------
// SelfAttention: B=4, S=2048, D=1024, fp32, softmax(Q K^T) V, no 1/sqrt(d).
// Round 1 baseline: pure fp32 SIMT GEMMs (precision-safe), 4 launches:
//   1) Q,K,V = x @ W{q,k,v}        (3x GEMM NN, 8192x1024x1024)
//   2) S = Q @ K^T  per batch      (GEMM NT, 2048x2048x1024, z=4)
//   3) rowwise softmax(S)          (max-subtracted)
//   4) O = S @ V    per batch      (GEMM NN, 2048x1024x2048, z=4)
// ---------------------------------------------------------------------------

#define BATCH 4
#define SEQ   2048
#define DIM   1024
#define MTOT  (BATCH * SEQ)   // 8192

// Static device scratch (no allocations allowed).
__device__ float g_Q[(size_t)MTOT * DIM];              // 32 MB
__device__ float g_K[(size_t)MTOT * DIM];              // 32 MB
__device__ float g_V[(size_t)MTOT * DIM];              // 32 MB
__device__ float g_S[(size_t)BATCH * SEQ * SEQ];       // 64 MB

#define BM 128
#define BN 128
#define BK 16
#define TM 8
#define TN 8
// 256 threads: 16x16 thread grid, each computes TMxTN.

template <bool TRANSB>
__global__ __launch_bounds__(256, 2)
void gemm_kernel(const float* __restrict__ A, const float* __restrict__ B,
                 float* __restrict__ C, int M, int N, int K,
                 size_t strideA, size_t strideB, size_t strideC)
{
    __shared__ float As[BK][BM + 4];
    __shared__ float Bs[BK][BN + 4];

    const int tid  = threadIdx.x;
    const int trow = tid >> 4;        // 0..15
    const int tcol = tid & 15;        // 0..15

    const int rowBase = blockIdx.y * BM;
    const int colBase = blockIdx.x * BN;

    A += (size_t)blockIdx.z * strideA;
    B += (size_t)blockIdx.z * strideB;
    C += (size_t)blockIdx.z * strideC;

    // Transposed-store loader indices (used for A always, and for B when NT)
    const int aRow = tid >> 2;          // 0..63 (m / n index)
    const int aCol = (tid & 3) << 2;    // k offset: 0,4,8,12

    // Direct-store loader indices (B when NN)
    const int bRow = tid >> 5;          // 0..7  (k index)
    const int bCol = (tid & 31) << 2;   // n offset

    float acc[TM][TN];
#pragma unroll
    for (int i = 0; i < TM; i++)
#pragma unroll
        for (int j = 0; j < TN; j++) acc[i][j] = 0.0f;

    for (int k0 = 0; k0 < K; k0 += BK) {
        // --- load A tile (M x K row-major), store transposed As[k][m] ---
#pragma unroll
        for (int off = 0; off < BM; off += 64) {
            const float4 t = *reinterpret_cast<const float4*>(
                &A[(size_t)(rowBase + aRow + off) * K + (k0 + aCol)]);
            As[aCol + 0][aRow + off] = t.x;
            As[aCol + 1][aRow + off] = t.y;
            As[aCol + 2][aRow + off] = t.z;
            As[aCol + 3][aRow + off] = t.w;
        }
        if (TRANSB) {
            // B stored N x K row-major; Bs[k][n] = B[n][k]
#pragma unroll
            for (int off = 0; off < BN; off += 64) {
                const float4 t = *reinterpret_cast<const float4*>(
                    &B[(size_t)(colBase + aRow + off) * K + (k0 + aCol)]);
                Bs[aCol + 0][aRow + off] = t.x;
                Bs[aCol + 1][aRow + off] = t.y;
                Bs[aCol + 2][aRow + off] = t.z;
                Bs[aCol + 3][aRow + off] = t.w;
            }
        } else {
            // B stored K x N row-major; direct vectorized copy
#pragma unroll
            for (int off = 0; off < BK; off += 8) {
                *reinterpret_cast<float4*>(&Bs[bRow + off][bCol]) =
                    *reinterpret_cast<const float4*>(
                        &B[(size_t)(k0 + bRow + off) * N + colBase + bCol]);
            }
        }
        __syncthreads();

#pragma unroll
        for (int kk = 0; kk < BK; kk++) {
            float ar[TM], br[TN];
            *reinterpret_cast<float4*>(&ar[0]) =
                *reinterpret_cast<const float4*>(&As[kk][trow * TM]);
            *reinterpret_cast<float4*>(&ar[4]) =
                *reinterpret_cast<const float4*>(&As[kk][trow * TM + 4]);
            *reinterpret_cast<float4*>(&br[0]) =
                *reinterpret_cast<const float4*>(&Bs[kk][tcol * TN]);
            *reinterpret_cast<float4*>(&br[4]) =
                *reinterpret_cast<const float4*>(&Bs[kk][tcol * TN + 4]);
#pragma unroll
            for (int i = 0; i < TM; i++)
#pragma unroll
                for (int j = 0; j < TN; j++)
                    acc[i][j] = fmaf(ar[i], br[j], acc[i][j]);
        }
        __syncthreads();
    }

    // --- epilogue ---
#pragma unroll
    for (int i = 0; i < TM; i++) {
        float* cptr = &C[(size_t)(rowBase + trow * TM + i) * N + colBase + tcol * TN];
        *reinterpret_cast<float4*>(cptr) =
            make_float4(acc[i][0], acc[i][1], acc[i][2], acc[i][3]);
        *reinterpret_cast<float4*>(cptr + 4) =
            make_float4(acc[i][4], acc[i][5], acc[i][6], acc[i][7]);
    }
}

// Row-wise softmax over SEQ=2048 columns, one CTA (256 threads) per row.
__global__ __launch_bounds__(256)
void softmax_kernel(float* __restrict__ S)
{
    float4* row = reinterpret_cast<float4*>(S + (size_t)blockIdx.x * SEQ);
    const int tid = threadIdx.x;

    float4 a = row[tid];
    float4 b = row[tid + 256];

    // --- max reduce ---
    float m = fmaxf(fmaxf(fmaxf(a.x, a.y), fmaxf(a.z, a.w)),
                    fmaxf(fmaxf(b.x, b.y), fmaxf(b.z, b.w)));
#pragma unroll
    for (int o = 16; o > 0; o >>= 1)
        m = fmaxf(m, __shfl_xor_sync(0xffffffffu, m, o));

    __shared__ float redmax[8];
    __shared__ float redsum[8];
    if ((tid & 31) == 0) redmax[tid >> 5] = m;
    __syncthreads();
    float mrow = redmax[0];
#pragma unroll
    for (int i = 1; i < 8; i++) mrow = fmaxf(mrow, redmax[i]);

    // --- exp + sum ---
    a.x = expf(a.x - mrow); a.y = expf(a.y - mrow);
    a.z = expf(a.z - mrow); a.w = expf(a.w - mrow);
    b.x = expf(b.x - mrow); b.y = expf(b.y - mrow);
    b.z = expf(b.z - mrow); b.w = expf(b.w - mrow);

    float s = (a.x + a.y) + (a.z + a.w) + (b.x + b.y) + (b.z + b.w);
#pragma unroll
    for (int o = 16; o > 0; o >>= 1)
        s += __shfl_xor_sync(0xffffffffu, s, o);
    if ((tid & 31) == 0) redsum[tid >> 5] = s;
    __syncthreads();
    float srow = 0.0f;
#pragma unroll
    for (int i = 0; i < 8; i++) srow += redsum[i];

    const float inv = 1.0f / srow;
    a.x *= inv; a.y *= inv; a.z *= inv; a.w *= inv;
    b.x *= inv; b.y *= inv; b.z *= inv; b.w *= inv;

    row[tid]       = a;
    row[tid + 256] = b;
}

extern "C" void kernel_launch(void* const* d_in, const int* in_sizes, int n_in,
                              void* d_out, int out_size)
{
    const float* x  = (const float*)d_in[0];
    const float* Wq = (const float*)d_in[1];
    const float* Wk = (const float*)d_in[2];
    const float* Wv = (const float*)d_in[3];
    float* out = (float*)d_out;

    float *Q, *K, *V, *S;
    cudaGetSymbolAddress((void**)&Q, g_Q);
    cudaGetSymbolAddress((void**)&K, g_K);
    cudaGetSymbolAddress((void**)&V, g_V);
    cudaGetSymbolAddress((void**)&S, g_S);

    // 1) Projections: [8192,1024] @ [1024,1024] (NN)
    {
        dim3 grid(DIM / BN, MTOT / BM, 1);
        gemm_kernel<false><<<grid, 256>>>(x, Wq, Q, MTOT, DIM, DIM, 0, 0, 0);
        gemm_kernel<false><<<grid, 256>>>(x, Wk, K, MTOT, DIM, DIM, 0, 0, 0);
        gemm_kernel<false><<<grid, 256>>>(x, Wv, V, MTOT, DIM, DIM, 0, 0, 0);
    }

    // 2) Scores: S[b] = Q[b] @ K[b]^T  (NT), per-batch
    {
        dim3 grid(SEQ / BN, SEQ / BM, BATCH);
        gemm_kernel<true><<<grid, 256>>>(Q, K, S, SEQ, SEQ, DIM,
                                         (size_t)SEQ * DIM,
                                         (size_t)SEQ * DIM,
                                         (size_t)SEQ * SEQ);
    }

    // 3) Softmax rows (B*S rows of length SEQ)
    softmax_kernel<<<BATCH * SEQ, 256>>>(S);

    // 4) Output: O[b] = S[b] @ V[b]  (NN), per-batch
    {
        dim3 grid(DIM / BN, SEQ / BM, BATCH);
        gemm_kernel<false><<<grid, 256>>>(S, V, out, SEQ, DIM, SEQ,
                                          (size_t)SEQ * SEQ,
                                          (size_t)SEQ * DIM,
                                          (size_t)SEQ * DIM);
    }
}

// round 3
// speedup vs baseline: 2.1024x; 2.1024x over previous
#include <cuda_runtime.h>
#include <cuda_bf16.h>
#include <cstdint>

// ---------------------------------------------------------------------------
// SelfAttention B=4, S=2048, D=1024 fp32.
// tcgen05 is unavailable (harness PTX target is sm_103, not sm_103a), so all
// GEMMs use baseline-PTX tensor cores: mma.sync.m16n8k16 bf16 + ldmatrix +
// cp.async double-buffered pipeline. Multi-word bf16 arithmetic:
//   projections:  2-split operands, 3 terms {00,01,10}
//   scores QK^T:  2-split operands, 4 terms {00,01,10,11}
//   AV:           2-split operands, 3 terms
// fp32 accumulation in registers.
// ---------------------------------------------------------------------------

#define BATCH 4
#define SEQ   2048
#define DIM   1024
#define MTOT  (BATCH * SEQ)   // 8192

#define AL __align__(128)
__device__ AL __nv_bfloat16 g_xp0[(size_t)MTOT * DIM];
__device__ AL __nv_bfloat16 g_xp1[(size_t)MTOT * DIM];
__device__ AL __nv_bfloat16 g_wqt0[(size_t)DIM * DIM];
__device__ AL __nv_bfloat16 g_wqt1[(size_t)DIM * DIM];
__device__ AL __nv_bfloat16 g_wkt0[(size_t)DIM * DIM];
__device__ AL __nv_bfloat16 g_wkt1[(size_t)DIM * DIM];
__device__ AL __nv_bfloat16 g_wvt0[(size_t)DIM * DIM];
__device__ AL __nv_bfloat16 g_wvt1[(size_t)DIM * DIM];
__device__ AL __nv_bfloat16 g_qp0[(size_t)MTOT * DIM];
__device__ AL __nv_bfloat16 g_qp1[(size_t)MTOT * DIM];
__device__ AL __nv_bfloat16 g_kp0[(size_t)MTOT * DIM];
__device__ AL __nv_bfloat16 g_kp1[(size_t)MTOT * DIM];
__device__ AL __nv_bfloat16 g_vp0[(size_t)MTOT * DIM];
__device__ AL __nv_bfloat16 g_vp1[(size_t)MTOT * DIM];
__device__ AL __nv_bfloat16 g_vtp0[(size_t)BATCH * DIM * SEQ];
__device__ AL __nv_bfloat16 g_vtp1[(size_t)BATCH * DIM * SEQ];
__device__ AL float         g_S[(size_t)BATCH * SEQ * SEQ];
__device__ AL __nv_bfloat16 g_pp0[(size_t)BATCH * SEQ * SEQ];
__device__ AL __nv_bfloat16 g_pp1[(size_t)BATCH * SEQ * SEQ];

// ---------------- PTX helpers ------------------------------------------------
__device__ __forceinline__ uint32_t smem_to_u32(const void* p) {
    uint32_t a;
    asm("{ .reg .u64 t; cvta.to.shared.u64 t, %1; cvt.u32.u64 %0, t; }"
        : "=r"(a) : "l"(p));
    return a;
}
#define CP_ASYNC_16(dst, src) \
    asm volatile("cp.async.cg.shared.global [%0], [%1], 16;" \
                 :: "r"(dst), "l"(src) : "memory")
#define CP_COMMIT() asm volatile("cp.async.commit_group;" ::: "memory")
#define CP_WAIT_1() asm volatile("cp.async.wait_group 1;" ::: "memory")

#define LDSM4(r0, r1, r2, r3, addr) \
    asm volatile("ldmatrix.sync.aligned.m8n8.x4.shared.b16 {%0,%1,%2,%3}, [%4];" \
                 : "=r"(r0), "=r"(r1), "=r"(r2), "=r"(r3) : "r"(addr))

#define MMA16816(d, a, b0r, b1r) \
    asm volatile("mma.sync.aligned.m16n8k16.row.col.f32.bf16.bf16.f32 " \
                 "{%0,%1,%2,%3}, {%4,%5,%6,%7}, {%8,%9}, {%0,%1,%2,%3};" \
                 : "+f"((d)[0]), "+f"((d)[1]), "+f"((d)[2]), "+f"((d)[3]) \
                 : "r"((a)[0]), "r"((a)[1]), "r"((a)[2]), "r"((a)[3]), \
                   "r"(b0r), "r"(b1r))

// ---------------- split helpers ----------------------------------------------
__device__ __forceinline__ uint32_t packbf2(__nv_bfloat16 a, __nv_bfloat16 b) {
    return (uint32_t)__bfloat16_as_ushort(a) | ((uint32_t)__bfloat16_as_ushort(b) << 16);
}
__device__ __forceinline__ void split2(float v, __nv_bfloat16& b0, __nv_bfloat16& b1) {
    b0 = __float2bfloat16(v);
    b1 = __float2bfloat16(v - __bfloat162float(b0));
}

// ---------------- GEMM: C[M,N] = sum_cb A_part[CIA] * B_part[CIB]^T -----------
// A parts: M x K row-major (K-major). B parts: N x K row-major (K-major).
// CTA tile 128x128, BK=32, 8 warps, warp tile 64x32 (2 warps M, 4 warps N).
// EPI: 0 = fp32 store to cf;  2 = 2-way bf16 split store to c0/c1.
template <int NCOMBO, int EPI>
__global__ void __launch_bounds__(256, 1)
gemm_mma(const __nv_bfloat16* __restrict__ a0, const __nv_bfloat16* __restrict__ a1,
         const __nv_bfloat16* __restrict__ b0, const __nv_bfloat16* __restrict__ b1,
         float* __restrict__ cf,
         __nv_bfloat16* __restrict__ c0, __nv_bfloat16* __restrict__ c1,
         int Ktot, int ldC, size_t strideA, size_t strideB, size_t strideC)
{
    constexpr int CIA[4] = {0, 0, 1, 1};
    constexpr int CIB[4] = {0, 1, 0, 1};

    extern __shared__ char dsm[];                // 2 stages * 4 tiles * 8192 B
    const uint32_t sbase = smem_to_u32(dsm);

    const int tid  = threadIdx.x;
    const int wid  = tid >> 5;
    const int lane = tid & 31;
    const int lrow = lane & 15;
    const int lch  = lane >> 4;

    const int wm = (wid & 1) * 64;   // warp M offset within CTA tile
    const int wn = (wid >> 1) * 32;  // warp N offset

    const int mBase = blockIdx.y * 128;
    const int nBase = blockIdx.x * 128;

    const size_t zA = (size_t)blockIdx.z * strideA;
    const size_t zB = (size_t)blockIdx.z * strideB;
    const size_t zC = (size_t)blockIdx.z * strideC;
    const __nv_bfloat16* ap[2] = { a0 + zA, a1 + zA };
    const __nv_bfloat16* bp[2] = { b0 + zB, b1 + zB };

    // smem row-swizzle: row stride 64B (32 bf16), 4 chunks of 16B per row,
    // stored chunk = c ^ ((row>>1)&3).  Conflict-free for STS.128 groups and
    // for ldmatrix 8-row phases (verified bank math).
    const int arsw = ((wm + lrow) >> 1) & 3;
    const int brsw = ((wn + lrow) >> 1) & 3;
    const uint32_t aoff = (uint32_t)(wm + lrow) * 64;
    const uint32_t boff = (uint32_t)(wn + lrow) * 64;

    float acc[4][4][4];
#pragma unroll
    for (int i = 0; i < 4; i++)
#pragma unroll
        for (int j = 0; j < 4; j++)
#pragma unroll
            for (int e = 0; e < 4; e++) acc[i][j][e] = 0.0f;

    const int NCHUNK = Ktot >> 5;

    auto load_stage = [&](int chunk, int buf) {
        const int k0 = chunk << 5;
        const uint32_t sb = sbase + (uint32_t)buf * 32768u;
#pragma unroll
        for (int t = 0; t < 4; ++t) {
            const __nv_bfloat16* src = (t < 2) ? ap[t] : bp[t - 2];
            const int rb = (t < 2) ? mBase : nBase;
            const uint32_t tb = sb + (uint32_t)t * 8192u;
#pragma unroll
            for (int i = 0; i < 2; ++i) {
                const int id  = tid + i * 256;      // 0..511
                const int row = id >> 2;
                const int c   = id & 3;
                const __nv_bfloat16* g = src + (size_t)(rb + row) * Ktot + k0 + c * 8;
                const uint32_t d = tb + (uint32_t)row * 64u +
                                   (uint32_t)((c ^ ((row >> 1) & 3)) * 16);
                CP_ASYNC_16(d, g);
            }
        }
    };

    load_stage(0, 0); CP_COMMIT();
    load_stage(1, 1); CP_COMMIT();

    for (int chunk = 0; chunk < NCHUNK; ++chunk) {
        const int buf = chunk & 1;
        CP_WAIT_1();
        __syncthreads();

        const uint32_t stb = sbase + (uint32_t)buf * 32768u;
#pragma unroll
        for (int cb = 0; cb < NCOMBO; ++cb) {
            const uint32_t abase = stb + (uint32_t)CIA[cb] * 8192u + aoff;
            const uint32_t bbase = stb + (uint32_t)(2 + CIB[cb]) * 8192u + boff;
#pragma unroll
            for (int k16 = 0; k16 < 2; ++k16) {
                const uint32_t asw = (uint32_t)(((k16 * 2 + lch) ^ arsw) * 16);
                const uint32_t bsw = (uint32_t)(((k16 * 2 + lch) ^ brsw) * 16);
                uint32_t afr[4][4];
#pragma unroll
                for (int im = 0; im < 4; ++im)
                    LDSM4(afr[im][0], afr[im][1], afr[im][2], afr[im][3],
                          abase + (uint32_t)im * 1024u + asw);
                uint32_t bfr[2][4];
#pragma unroll
                for (int g = 0; g < 2; ++g)
                    LDSM4(bfr[g][0], bfr[g][1], bfr[g][2], bfr[g][3],
                          bbase + (uint32_t)g * 1024u + bsw);
#pragma unroll
                for (int im = 0; im < 4; ++im)
#pragma unroll
                    for (int in = 0; in < 4; ++in)
                        MMA16816(acc[im][in], afr[im],
                                 bfr[in >> 1][in & 1], bfr[in >> 1][(in & 1) + 2]);
            }
        }
        __syncthreads();
        if (chunk + 2 < NCHUNK) load_stage(chunk + 2, buf);
        CP_COMMIT();   // always commit so wait_group(1) counts stay aligned
    }

    // ---------------- epilogue ----------------
    const int quad = lane >> 2;       // 0..7
    const int tcol = lane & 3;        // 0..3
#pragma unroll
    for (int im = 0; im < 4; ++im) {
#pragma unroll
        for (int in = 0; in < 4; ++in) {
            const int row = mBase + wm + im * 16 + quad;
            const int col = nBase + wn + in * 8 + tcol * 2;
            if constexpr (EPI == 0) {
                float2* plo = reinterpret_cast<float2*>(cf + zC + (size_t)row * ldC + col);
                float2* phi = reinterpret_cast<float2*>(cf + zC + (size_t)(row + 8) * ldC + col);
                *plo = make_float2(acc[im][in][0], acc[im][in][1]);
                *phi = make_float2(acc[im][in][2], acc[im][in][3]);
            } else {
                __nv_bfloat16 xh, xl, yh, yl;
                const size_t olo = zC + (size_t)row * ldC + col;
                const size_t ohi = zC + (size_t)(row + 8) * ldC + col;
                split2(acc[im][in][0], xh, xl); split2(acc[im][in][1], yh, yl);
                *reinterpret_cast<uint32_t*>(c0 + olo) = packbf2(xh, yh);
                *reinterpret_cast<uint32_t*>(c1 + olo) = packbf2(xl, yl);
                split2(acc[im][in][2], xh, xl); split2(acc[im][in][3], yh, yl);
                *reinterpret_cast<uint32_t*>(c0 + ohi) = packbf2(xh, yh);
                *reinterpret_cast<uint32_t*>(c1 + ohi) = packbf2(xl, yl);
            }
        }
    }
}

// ---------------- aux kernels --------------------------------------------------
__global__ void __launch_bounds__(256)
split2_kernel(const float* __restrict__ src, __nv_bfloat16* __restrict__ d0,
              __nv_bfloat16* __restrict__ d1)
{
    const size_t i = (size_t)blockIdx.x * 256 + threadIdx.x;
    const float4 v = reinterpret_cast<const float4*>(src)[i];
    __nv_bfloat16 a0, a1, b0, b1, c0, c1, e0, e1;
    split2(v.x, a0, a1); split2(v.y, b0, b1);
    split2(v.z, c0, c1); split2(v.w, e0, e1);
    reinterpret_cast<uint2*>(d0)[i] = make_uint2(packbf2(a0, b0), packbf2(c0, e0));
    reinterpret_cast<uint2*>(d1)[i] = make_uint2(packbf2(a1, b1), packbf2(c1, e1));
}

// W [K,N] fp32 -> transposed 2-way split Wt parts [N,K] bf16
__global__ void __launch_bounds__(256)
wsplit_kernel(const float* __restrict__ W, __nv_bfloat16* __restrict__ t0,
              __nv_bfloat16* __restrict__ t1)
{
    __shared__ float tile[32][33];
    const int tx = threadIdx.x, ty = threadIdx.y;
    const int k0 = blockIdx.y * 32, n0 = blockIdx.x * 32;
#pragma unroll
    for (int i = 0; i < 4; ++i)
        tile[ty + i * 8][tx] = W[(size_t)(k0 + ty + i * 8) * DIM + n0 + tx];
    __syncthreads();
#pragma unroll
    for (int i = 0; i < 4; ++i) {
        const int n = n0 + ty + i * 8;
        const float v = tile[tx][ty + i * 8];
        __nv_bfloat16 b0, b1;
        split2(v, b0, b1);
        t0[(size_t)n * DIM + k0 + tx] = b0;
        t1[(size_t)n * DIM + k0 + tx] = b1;
    }
}

// V parts [B*S, D] bf16 -> Vt parts [B][D][S] bf16
__global__ void __launch_bounds__(256)
vtrans_kernel(const __nv_bfloat16* __restrict__ v0, const __nv_bfloat16* __restrict__ v1,
              __nv_bfloat16* __restrict__ t0, __nv_bfloat16* __restrict__ t1)
{
    __shared__ __nv_bfloat16 tile[32][33];
    const int z = blockIdx.z, b = z >> 1, part = z & 1;
    const __nv_bfloat16* src = part ? v1 : v0;
    __nv_bfloat16* dst = part ? t1 : t0;
    const int tx = threadIdx.x, ty = threadIdx.y;
    const int s0 = blockIdx.x * 32, d0 = blockIdx.y * 32;
#pragma unroll
    for (int i = 0; i < 4; ++i)
        tile[ty + i * 8][tx] = src[((size_t)b * SEQ + s0 + ty + i * 8) * DIM + d0 + tx];
    __syncthreads();
#pragma unroll
    for (int i = 0; i < 4; ++i)
        dst[(size_t)b * DIM * SEQ + (size_t)(d0 + ty + i * 8) * SEQ + s0 + tx] =
            tile[tx][ty + i * 8];
}

// row softmax of S (fp32, row length SEQ) -> 2-way bf16 split P
__global__ void __launch_bounds__(256)
softmax_kernel(const float* __restrict__ S, __nv_bfloat16* __restrict__ p0,
               __nv_bfloat16* __restrict__ p1)
{
    const float4* row = reinterpret_cast<const float4*>(S + (size_t)blockIdx.x * SEQ);
    const int tid = threadIdx.x;

    float4 a = row[tid];
    float4 b = row[tid + 256];

    float m = fmaxf(fmaxf(fmaxf(a.x, a.y), fmaxf(a.z, a.w)),
                    fmaxf(fmaxf(b.x, b.y), fmaxf(b.z, b.w)));
#pragma unroll
    for (int o = 16; o > 0; o >>= 1) m = fmaxf(m, __shfl_xor_sync(0xffffffffu, m, o));

    __shared__ float redmax[8];
    __shared__ float redsum[8];
    if ((tid & 31) == 0) redmax[tid >> 5] = m;
    __syncthreads();
    float mrow = redmax[0];
#pragma unroll
    for (int i = 1; i < 8; ++i) mrow = fmaxf(mrow, redmax[i]);

    a.x = expf(a.x - mrow); a.y = expf(a.y - mrow);
    a.z = expf(a.z - mrow); a.w = expf(a.w - mrow);
    b.x = expf(b.x - mrow); b.y = expf(b.y - mrow);
    b.z = expf(b.z - mrow); b.w = expf(b.w - mrow);

    float s = (a.x + a.y) + (a.z + a.w) + (b.x + b.y) + (b.z + b.w);
#pragma unroll
    for (int o = 16; o > 0; o >>= 1) s += __shfl_xor_sync(0xffffffffu, s, o);
    if ((tid & 31) == 0) redsum[tid >> 5] = s;
    __syncthreads();
    float srow = 0.0f;
#pragma unroll
    for (int i = 0; i < 8; ++i) srow += redsum[i];
    const float inv = 1.0f / srow;

    uint2* r0 = reinterpret_cast<uint2*>(p0 + (size_t)blockIdx.x * SEQ);
    uint2* r1 = reinterpret_cast<uint2*>(p1 + (size_t)blockIdx.x * SEQ);
    __nv_bfloat16 h0, l0, h1, l1, h2, l2, h3, l3;

    split2(a.x * inv, h0, l0); split2(a.y * inv, h1, l1);
    split2(a.z * inv, h2, l2); split2(a.w * inv, h3, l3);
    r0[tid] = make_uint2(packbf2(h0, h1), packbf2(h2, h3));
    r1[tid] = make_uint2(packbf2(l0, l1), packbf2(l2, l3));

    split2(b.x * inv, h0, l0); split2(b.y * inv, h1, l1);
    split2(b.z * inv, h2, l2); split2(b.w * inv, h3, l3);
    r0[tid + 256] = make_uint2(packbf2(h0, h1), packbf2(h2, h3));
    r1[tid + 256] = make_uint2(packbf2(l0, l1), packbf2(l2, l3));
}

// ---------------- launch --------------------------------------------------------
extern "C" void kernel_launch(void* const* d_in, const int* in_sizes, int n_in,
                              void* d_out, int out_size)
{
    const float* x  = (const float*)d_in[0];
    const float* Wq = (const float*)d_in[1];
    const float* Wk = (const float*)d_in[2];
    const float* Wv = (const float*)d_in[3];
    float* out = (float*)d_out;

    __nv_bfloat16 *xp0, *xp1, *wqt0, *wqt1, *wkt0, *wkt1, *wvt0, *wvt1;
    __nv_bfloat16 *qp0, *qp1, *kp0, *kp1, *vp0, *vp1, *vtp0, *vtp1, *pp0, *pp1;
    float* S;
    cudaGetSymbolAddress((void**)&xp0, g_xp0);   cudaGetSymbolAddress((void**)&xp1, g_xp1);
    cudaGetSymbolAddress((void**)&wqt0, g_wqt0); cudaGetSymbolAddress((void**)&wqt1, g_wqt1);
    cudaGetSymbolAddress((void**)&wkt0, g_wkt0); cudaGetSymbolAddress((void**)&wkt1, g_wkt1);
    cudaGetSymbolAddress((void**)&wvt0, g_wvt0); cudaGetSymbolAddress((void**)&wvt1, g_wvt1);
    cudaGetSymbolAddress((void**)&qp0, g_qp0);   cudaGetSymbolAddress((void**)&qp1, g_qp1);
    cudaGetSymbolAddress((void**)&kp0, g_kp0);   cudaGetSymbolAddress((void**)&kp1, g_kp1);
    cudaGetSymbolAddress((void**)&vp0, g_vp0);   cudaGetSymbolAddress((void**)&vp1, g_vp1);
    cudaGetSymbolAddress((void**)&vtp0, g_vtp0); cudaGetSymbolAddress((void**)&vtp1, g_vtp1);
    cudaGetSymbolAddress((void**)&pp0, g_pp0);   cudaGetSymbolAddress((void**)&pp1, g_pp1);
    cudaGetSymbolAddress((void**)&S, g_S);

    const int SMEM = 2 * 4 * 8192;  // 65536
    cudaFuncSetAttribute(gemm_mma<3, 2>, cudaFuncAttributeMaxDynamicSharedMemorySize, SMEM);
    cudaFuncSetAttribute(gemm_mma<4, 0>, cudaFuncAttributeMaxDynamicSharedMemorySize, SMEM);
    cudaFuncSetAttribute(gemm_mma<3, 0>, cudaFuncAttributeMaxDynamicSharedMemorySize, SMEM);

    // 1) operand splits
    split2_kernel<<<(MTOT * DIM) / 1024, 256>>>(x, xp0, xp1);
    {
        dim3 g(DIM / 32, DIM / 32), blk(32, 8);
        wsplit_kernel<<<g, blk>>>(Wq, wqt0, wqt1);
        wsplit_kernel<<<g, blk>>>(Wk, wkt0, wkt1);
        wsplit_kernel<<<g, blk>>>(Wv, wvt0, wvt1);
    }

    // 2) projections: [8192,1024] x [1024,1024]^T(K-major), 3 combos, split2 out
    {
        dim3 g(DIM / 128, MTOT / 128, 1);
        gemm_mma<3, 2><<<g, 256, SMEM>>>(xp0, xp1, wqt0, wqt1,
                                         nullptr, qp0, qp1, DIM, DIM, 0, 0, 0);
        gemm_mma<3, 2><<<g, 256, SMEM>>>(xp0, xp1, wkt0, wkt1,
                                         nullptr, kp0, kp1, DIM, DIM, 0, 0, 0);
        gemm_mma<3, 2><<<g, 256, SMEM>>>(xp0, xp1, wvt0, wvt1,
                                         nullptr, vp0, vp1, DIM, DIM, 0, 0, 0);
    }

    // 3) V transpose (per batch, both parts)
    {
        dim3 g(SEQ / 32, DIM / 32, BATCH * 2), blk(32, 8);
        vtrans_kernel<<<g, blk>>>(vp0, vp1, vtp0, vtp1);
    }

    // 4) scores S[b] = Q[b] @ K[b]^T, 4 combos, fp32 out
    {
        dim3 g(SEQ / 128, SEQ / 128, BATCH);
        gemm_mma<4, 0><<<g, 256, SMEM>>>(qp0, qp1, kp0, kp1,
                                         S, nullptr, nullptr,
                                         DIM, SEQ,
                                         (size_t)SEQ * DIM, (size_t)SEQ * DIM,
                                         (size_t)SEQ * SEQ);
    }

    // 5) softmax -> P parts (2-split bf16)
    softmax_kernel<<<BATCH * SEQ, 256>>>(S, pp0, pp1);

    // 6) O[b] = P[b] @ Vt[b]^T, 3 combos, fp32 out
    {
        dim3 g(DIM / 128, SEQ / 128, BATCH);
        gemm_mma<3, 0><<<g, 256, SMEM>>>(pp0, pp1, vtp0, vtp1,
                                         out, nullptr, nullptr,
                                         SEQ, DIM,
                                         (size_t)SEQ * SEQ, (size_t)DIM * SEQ,
                                         (size_t)SEQ * DIM);
    }
}

// round 4
// speedup vs baseline: 2.3563x; 1.1207x over previous
#include <cuda_runtime.h>
#include <cuda_bf16.h>
#include <cstdint>

// ---------------------------------------------------------------------------
// SelfAttention B=4, S=2048, D=1024 fp32.
// mma.sync.m16n8k16 bf16 + ldmatrix + cp.async double-buffered pipeline.
// Multi-word bf16: projections 3 terms, scores 3 terms (q1k1 negligible),
// AV 3 terms. fp32 accumulate.
// R4: warp tile 64x64 (CTA 128x256), scores drop {11} combo, __expf softmax.
// ---------------------------------------------------------------------------

#define BATCH 4
#define SEQ   2048
#define DIM   1024
#define MTOT  (BATCH * SEQ)   // 8192

#define AL __align__(128)
__device__ AL __nv_bfloat16 g_xp0[(size_t)MTOT * DIM];
__device__ AL __nv_bfloat16 g_xp1[(size_t)MTOT * DIM];
__device__ AL __nv_bfloat16 g_wqt0[(size_t)DIM * DIM];
__device__ AL __nv_bfloat16 g_wqt1[(size_t)DIM * DIM];
__device__ AL __nv_bfloat16 g_wkt0[(size_t)DIM * DIM];
__device__ AL __nv_bfloat16 g_wkt1[(size_t)DIM * DIM];
__device__ AL __nv_bfloat16 g_wvt0[(size_t)DIM * DIM];
__device__ AL __nv_bfloat16 g_wvt1[(size_t)DIM * DIM];
__device__ AL __nv_bfloat16 g_qp0[(size_t)MTOT * DIM];
__device__ AL __nv_bfloat16 g_qp1[(size_t)MTOT * DIM];
__device__ AL __nv_bfloat16 g_kp0[(size_t)MTOT * DIM];
__device__ AL __nv_bfloat16 g_kp1[(size_t)MTOT * DIM];
__device__ AL __nv_bfloat16 g_vp0[(size_t)MTOT * DIM];
__device__ AL __nv_bfloat16 g_vp1[(size_t)MTOT * DIM];
__device__ AL __nv_bfloat16 g_vtp0[(size_t)BATCH * DIM * SEQ];
__device__ AL __nv_bfloat16 g_vtp1[(size_t)BATCH * DIM * SEQ];
__device__ AL float         g_S[(size_t)BATCH * SEQ * SEQ];
__device__ AL __nv_bfloat16 g_pp0[(size_t)BATCH * SEQ * SEQ];
__device__ AL __nv_bfloat16 g_pp1[(size_t)BATCH * SEQ * SEQ];

// ---------------- PTX helpers ------------------------------------------------
__device__ __forceinline__ uint32_t smem_to_u32(const void* p) {
    uint32_t a;
    asm("{ .reg .u64 t; cvta.to.shared.u64 t, %1; cvt.u32.u64 %0, t; }"
        : "=r"(a) : "l"(p));
    return a;
}
#define CP_ASYNC_16(dst, src) \
    asm volatile("cp.async.cg.shared.global [%0], [%1], 16;" \
                 :: "r"(dst), "l"(src) : "memory")
#define CP_COMMIT() asm volatile("cp.async.commit_group;" ::: "memory")
#define CP_WAIT_1() asm volatile("cp.async.wait_group 1;" ::: "memory")

#define LDSM4(r0, r1, r2, r3, addr) \
    asm volatile("ldmatrix.sync.aligned.m8n8.x4.shared.b16 {%0,%1,%2,%3}, [%4];" \
                 : "=r"(r0), "=r"(r1), "=r"(r2), "=r"(r3) : "r"(addr))

#define MMA16816(d, a, b0r, b1r) \
    asm volatile("mma.sync.aligned.m16n8k16.row.col.f32.bf16.bf16.f32 " \
                 "{%0,%1,%2,%3}, {%4,%5,%6,%7}, {%8,%9}, {%0,%1,%2,%3};" \
                 : "+f"((d)[0]), "+f"((d)[1]), "+f"((d)[2]), "+f"((d)[3]) \
                 : "r"((a)[0]), "r"((a)[1]), "r"((a)[2]), "r"((a)[3]), \
                   "r"(b0r), "r"(b1r))

// ---------------- split helpers ----------------------------------------------
__device__ __forceinline__ uint32_t packbf2(__nv_bfloat16 a, __nv_bfloat16 b) {
    return (uint32_t)__bfloat16_as_ushort(a) | ((uint32_t)__bfloat16_as_ushort(b) << 16);
}
__device__ __forceinline__ void split2(float v, __nv_bfloat16& b0, __nv_bfloat16& b1) {
    b0 = __float2bfloat16(v);
    b1 = __float2bfloat16(v - __bfloat162float(b0));
}

// ---------------- GEMM: C[M,N] = sum_cb A_part[CIA] * B_part[CIB]^T -----------
// A parts: M x K row-major (K-major). B parts: N x K row-major (K-major).
// CTA tile 128x256, BK=32, 8 warps (2 M x 4 N), warp tile 64x64.
// smem per stage: A0,A1 (8KB each) + B0,B1 (16KB each) = 48KB; 2 stages.
// EPI: 0 = fp32 store to cf;  2 = 2-way bf16 split store to c0/c1.
template <int NCOMBO, int EPI>
__global__ void __launch_bounds__(256, 1)
gemm_mma(const __nv_bfloat16* __restrict__ a0, const __nv_bfloat16* __restrict__ a1,
         const __nv_bfloat16* __restrict__ b0, const __nv_bfloat16* __restrict__ b1,
         float* __restrict__ cf,
         __nv_bfloat16* __restrict__ c0, __nv_bfloat16* __restrict__ c1,
         int Ktot, int ldC, size_t strideA, size_t strideB, size_t strideC)
{
    constexpr int CIA[4] = {0, 0, 1, 1};
    constexpr int CIB[4] = {0, 1, 0, 1};
    constexpr uint32_t STG = 49152u;   // stage stride
    constexpr uint32_t B_OFF = 16384u; // B tiles start within a stage

    extern __shared__ char dsm[];
    const uint32_t sbase = smem_to_u32(dsm);

    const int tid  = threadIdx.x;
    const int wid  = tid >> 5;
    const int lane = tid & 31;
    const int lrow = lane & 15;
    const int lch  = lane >> 4;

    const int wm = (wid & 1) * 64;    // warp M offset
    const int wn = (wid >> 1) * 64;   // warp N offset

    const int mBase = blockIdx.y * 128;
    const int nBase = blockIdx.x * 256;

    const size_t zA = (size_t)blockIdx.z * strideA;
    const size_t zB = (size_t)blockIdx.z * strideB;
    const size_t zC = (size_t)blockIdx.z * strideC;
    const __nv_bfloat16* ap[2] = { a0 + zA, a1 + zA };
    const __nv_bfloat16* bp[2] = { b0 + zB, b1 + zB };

    const int arsw = ((wm + lrow) >> 1) & 3;
    const int brsw = ((wn + lrow) >> 1) & 3;
    const uint32_t aoff = (uint32_t)(wm + lrow) * 64;
    const uint32_t boff = (uint32_t)(wn + lrow) * 64;

    float acc[4][8][4];
#pragma unroll
    for (int i = 0; i < 4; i++)
#pragma unroll
        for (int j = 0; j < 8; j++)
#pragma unroll
            for (int e = 0; e < 4; e++) acc[i][j][e] = 0.0f;

    const int NCHUNK = Ktot >> 5;

    auto load_stage = [&](int chunk, int buf) {
        const int k0 = chunk << 5;
        const uint32_t sb = sbase + (uint32_t)buf * STG;
        // A tiles: 128 rows x 32 cols, 2 parts
#pragma unroll
        for (int t = 0; t < 2; ++t) {
            const uint32_t tb = sb + (uint32_t)t * 8192u;
#pragma unroll
            for (int i = 0; i < 2; ++i) {
                const int id  = tid + i * 256;      // 0..511
                const int row = id >> 2;
                const int c   = id & 3;
                const __nv_bfloat16* g = ap[t] + (size_t)(mBase + row) * Ktot + k0 + c * 8;
                const uint32_t d = tb + (uint32_t)row * 64u +
                                   (uint32_t)((c ^ ((row >> 1) & 3)) * 16);
                CP_ASYNC_16(d, g);
            }
        }
        // B tiles: 256 rows x 32 cols, 2 parts
#pragma unroll
        for (int t = 0; t < 2; ++t) {
            const uint32_t tb = sb + B_OFF + (uint32_t)t * 16384u;
#pragma unroll
            for (int i = 0; i < 4; ++i) {
                const int id  = tid + i * 256;      // 0..1023
                const int row = id >> 2;
                const int c   = id & 3;
                const __nv_bfloat16* g = bp[t] + (size_t)(nBase + row) * Ktot + k0 + c * 8;
                const uint32_t d = tb + (uint32_t)row * 64u +
                                   (uint32_t)((c ^ ((row >> 1) & 3)) * 16);
                CP_ASYNC_16(d, g);
            }
        }
    };

    load_stage(0, 0); CP_COMMIT();
    load_stage(1, 1); CP_COMMIT();

    for (int chunk = 0; chunk < NCHUNK; ++chunk) {
        const int buf = chunk & 1;
        CP_WAIT_1();
        __syncthreads();

        const uint32_t stb = sbase + (uint32_t)buf * STG;
#pragma unroll
        for (int cb = 0; cb < NCOMBO; ++cb) {
            const uint32_t abase = stb + (uint32_t)CIA[cb] * 8192u + aoff;
            const uint32_t bbase = stb + B_OFF + (uint32_t)CIB[cb] * 16384u + boff;
#pragma unroll
            for (int k16 = 0; k16 < 2; ++k16) {
                const uint32_t asw = (uint32_t)(((k16 * 2 + lch) ^ arsw) * 16);
                const uint32_t bsw = (uint32_t)(((k16 * 2 + lch) ^ brsw) * 16);
                uint32_t afr[4][4];
#pragma unroll
                for (int im = 0; im < 4; ++im)
                    LDSM4(afr[im][0], afr[im][1], afr[im][2], afr[im][3],
                          abase + (uint32_t)im * 1024u + asw);
                uint32_t bfr[4][4];
#pragma unroll
                for (int g = 0; g < 4; ++g)
                    LDSM4(bfr[g][0], bfr[g][1], bfr[g][2], bfr[g][3],
                          bbase + (uint32_t)g * 1024u + bsw);
#pragma unroll
                for (int im = 0; im < 4; ++im)
#pragma unroll
                    for (int in = 0; in < 8; ++in)
                        MMA16816(acc[im][in], afr[im],
                                 bfr[in >> 1][in & 1], bfr[in >> 1][(in & 1) + 2]);
            }
        }
        __syncthreads();
        if (chunk + 2 < NCHUNK) load_stage(chunk + 2, buf);
        CP_COMMIT();   // keep group counts aligned with wait_group(1)
    }

    // ---------------- epilogue ----------------
    const int quad = lane >> 2;       // 0..7
    const int tcol = lane & 3;        // 0..3
#pragma unroll
    for (int im = 0; im < 4; ++im) {
#pragma unroll
        for (int in = 0; in < 8; ++in) {
            const int row = mBase + wm + im * 16 + quad;
            const int col = nBase + wn + in * 8 + tcol * 2;
            if constexpr (EPI == 0) {
                float2* plo = reinterpret_cast<float2*>(cf + zC + (size_t)row * ldC + col);
                float2* phi = reinterpret_cast<float2*>(cf + zC + (size_t)(row + 8) * ldC + col);
                *plo = make_float2(acc[im][in][0], acc[im][in][1]);
                *phi = make_float2(acc[im][in][2], acc[im][in][3]);
            } else {
                __nv_bfloat16 xh, xl, yh, yl;
                const size_t olo = zC + (size_t)row * ldC + col;
                const size_t ohi = zC + (size_t)(row + 8) * ldC + col;
                split2(acc[im][in][0], xh, xl); split2(acc[im][in][1], yh, yl);
                *reinterpret_cast<uint32_t*>(c0 + olo) = packbf2(xh, yh);
                *reinterpret_cast<uint32_t*>(c1 + olo) = packbf2(xl, yl);
                split2(acc[im][in][2], xh, xl); split2(acc[im][in][3], yh, yl);
                *reinterpret_cast<uint32_t*>(c0 + ohi) = packbf2(xh, yh);
                *reinterpret_cast<uint32_t*>(c1 + ohi) = packbf2(xl, yl);
            }
        }
    }
}

// ---------------- aux kernels --------------------------------------------------
__global__ void __launch_bounds__(256)
split2_kernel(const float* __restrict__ src, __nv_bfloat16* __restrict__ d0,
              __nv_bfloat16* __restrict__ d1)
{
    const size_t i = (size_t)blockIdx.x * 256 + threadIdx.x;
    const float4 v = reinterpret_cast<const float4*>(src)[i];
    __nv_bfloat16 a0, a1, b0, b1, c0, c1, e0, e1;
    split2(v.x, a0, a1); split2(v.y, b0, b1);
    split2(v.z, c0, c1); split2(v.w, e0, e1);
    reinterpret_cast<uint2*>(d0)[i] = make_uint2(packbf2(a0, b0), packbf2(c0, e0));
    reinterpret_cast<uint2*>(d1)[i] = make_uint2(packbf2(a1, b1), packbf2(c1, e1));
}

// W [K,N] fp32 -> transposed 2-way split Wt parts [N,K] bf16
__global__ void __launch_bounds__(256)
wsplit_kernel(const float* __restrict__ W, __nv_bfloat16* __restrict__ t0,
              __nv_bfloat16* __restrict__ t1)
{
    __shared__ float tile[32][33];
    const int tx = threadIdx.x, ty = threadIdx.y;
    const int k0 = blockIdx.y * 32, n0 = blockIdx.x * 32;
#pragma unroll
    for (int i = 0; i < 4; ++i)
        tile[ty + i * 8][tx] = W[(size_t)(k0 + ty + i * 8) * DIM + n0 + tx];
    __syncthreads();
#pragma unroll
    for (int i = 0; i < 4; ++i) {
        const int n = n0 + ty + i * 8;
        const float v = tile[tx][ty + i * 8];
        __nv_bfloat16 b0, b1;
        split2(v, b0, b1);
        t0[(size_t)n * DIM + k0 + tx] = b0;
        t1[(size_t)n * DIM + k0 + tx] = b1;
    }
}

// V parts [B*S, D] bf16 -> Vt parts [B][D][S] bf16
__global__ void __launch_bounds__(256)
vtrans_kernel(const __nv_bfloat16* __restrict__ v0, const __nv_bfloat16* __restrict__ v1,
              __nv_bfloat16* __restrict__ t0, __nv_bfloat16* __restrict__ t1)
{
    __shared__ __nv_bfloat16 tile[32][33];
    const int z = blockIdx.z, b = z >> 1, part = z & 1;
    const __nv_bfloat16* src = part ? v1 : v0;
    __nv_bfloat16* dst = part ? t1 : t0;
    const int tx = threadIdx.x, ty = threadIdx.y;
    const int s0 = blockIdx.x * 32, d0 = blockIdx.y * 32;
#pragma unroll
    for (int i = 0; i < 4; ++i)
        tile[ty + i * 8][tx] = src[((size_t)b * SEQ + s0 + ty + i * 8) * DIM + d0 + tx];
    __syncthreads();
#pragma unroll
    for (int i = 0; i < 4; ++i)
        dst[(size_t)b * DIM * SEQ + (size_t)(d0 + ty + i * 8) * SEQ + s0 + tx] =
            tile[tx][ty + i * 8];
}

// row softmax of S (fp32, row length SEQ) -> 2-way bf16 split P
__global__ void __launch_bounds__(256)
softmax_kernel(const float* __restrict__ S, __nv_bfloat16* __restrict__ p0,
               __nv_bfloat16* __restrict__ p1)
{
    const float4* row = reinterpret_cast<const float4*>(S + (size_t)blockIdx.x * SEQ);
    const int tid = threadIdx.x;

    float4 a = row[tid];
    float4 b = row[tid + 256];

    float m = fmaxf(fmaxf(fmaxf(a.x, a.y), fmaxf(a.z, a.w)),
                    fmaxf(fmaxf(b.x, b.y), fmaxf(b.z, b.w)));
#pragma unroll
    for (int o = 16; o > 0; o >>= 1) m = fmaxf(m, __shfl_xor_sync(0xffffffffu, m, o));

    __shared__ float redmax[8];
    __shared__ float redsum[8];
    if ((tid & 31) == 0) redmax[tid >> 5] = m;
    __syncthreads();
    float mrow = redmax[0];
#pragma unroll
    for (int i = 1; i < 8; ++i) mrow = fmaxf(mrow, redmax[i]);

    a.x = __expf(a.x - mrow); a.y = __expf(a.y - mrow);
    a.z = __expf(a.z - mrow); a.w = __expf(a.w - mrow);
    b.x = __expf(b.x - mrow); b.y = __expf(b.y - mrow);
    b.z = __expf(b.z - mrow); b.w = __expf(b.w - mrow);

    float s = (a.x + a.y) + (a.z + a.w) + (b.x + b.y) + (b.z + b.w);
#pragma unroll
    for (int o = 16; o > 0; o >>= 1) s += __shfl_xor_sync(0xffffffffu, s, o);
    if ((tid & 31) == 0) redsum[tid >> 5] = s;
    __syncthreads();
    float srow = 0.0f;
#pragma unroll
    for (int i = 0; i < 8; ++i) srow += redsum[i];
    const float inv = 1.0f / srow;

    uint2* r0 = reinterpret_cast<uint2*>(p0 + (size_t)blockIdx.x * SEQ);
    uint2* r1 = reinterpret_cast<uint2*>(p1 + (size_t)blockIdx.x * SEQ);
    __nv_bfloat16 h0, l0, h1, l1, h2, l2, h3, l3;

    split2(a.x * inv, h0, l0); split2(a.y * inv, h1, l1);
    split2(a.z * inv, h2, l2); split2(a.w * inv, h3, l3);
    r0[tid] = make_uint2(packbf2(h0, h1), packbf2(h2, h3));
    r1[tid] = make_uint2(packbf2(l0, l1), packbf2(l2, l3));

    split2(b.x * inv, h0, l0); split2(b.y * inv, h1, l1);
    split2(b.z * inv, h2, l2); split2(b.w * inv, h3, l3);
    r0[tid + 256] = make_uint2(packbf2(h0, h1), packbf2(h2, h3));
    r1[tid + 256] = make_uint2(packbf2(l0, l1), packbf2(l2, l3));
}

// ---------------- launch --------------------------------------------------------
extern "C" void kernel_launch(void* const* d_in, const int* in_sizes, int n_in,
                              void* d_out, int out_size)
{
    const float* x  = (const float*)d_in[0];
    const float* Wq = (const float*)d_in[1];
    const float* Wk = (const float*)d_in[2];
    const float* Wv = (const float*)d_in[3];
    float* out = (float*)d_out;

    __nv_bfloat16 *xp0, *xp1, *wqt0, *wqt1, *wkt0, *wkt1, *wvt0, *wvt1;
    __nv_bfloat16 *qp0, *qp1, *kp0, *kp1, *vp0, *vp1, *vtp0, *vtp1, *pp0, *pp1;
    float* S;
    cudaGetSymbolAddress((void**)&xp0, g_xp0);   cudaGetSymbolAddress((void**)&xp1, g_xp1);
    cudaGetSymbolAddress((void**)&wqt0, g_wqt0); cudaGetSymbolAddress((void**)&wqt1, g_wqt1);
    cudaGetSymbolAddress((void**)&wkt0, g_wkt0); cudaGetSymbolAddress((void**)&wkt1, g_wkt1);
    cudaGetSymbolAddress((void**)&wvt0, g_wvt0); cudaGetSymbolAddress((void**)&wvt1, g_wvt1);
    cudaGetSymbolAddress((void**)&qp0, g_qp0);   cudaGetSymbolAddress((void**)&qp1, g_qp1);
    cudaGetSymbolAddress((void**)&kp0, g_kp0);   cudaGetSymbolAddress((void**)&kp1, g_kp1);
    cudaGetSymbolAddress((void**)&vp0, g_vp0);   cudaGetSymbolAddress((void**)&vp1, g_vp1);
    cudaGetSymbolAddress((void**)&vtp0, g_vtp0); cudaGetSymbolAddress((void**)&vtp1, g_vtp1);
    cudaGetSymbolAddress((void**)&pp0, g_pp0);   cudaGetSymbolAddress((void**)&pp1, g_pp1);
    cudaGetSymbolAddress((void**)&S, g_S);

    const int SMEM = 2 * 49152;  // 98304
    cudaFuncSetAttribute(gemm_mma<3, 2>, cudaFuncAttributeMaxDynamicSharedMemorySize, SMEM);
    cudaFuncSetAttribute(gemm_mma<3, 0>, cudaFuncAttributeMaxDynamicSharedMemorySize, SMEM);

    // 1) operand splits
    split2_kernel<<<(MTOT * DIM) / 1024, 256>>>(x, xp0, xp1);
    {
        dim3 g(DIM / 32, DIM / 32), blk(32, 8);
        wsplit_kernel<<<g, blk>>>(Wq, wqt0, wqt1);
        wsplit_kernel<<<g, blk>>>(Wk, wkt0, wkt1);
        wsplit_kernel<<<g, blk>>>(Wv, wvt0, wvt1);
    }

    // 2) projections: [8192,1024] x [1024,1024]^T(K-major), 3 combos, split2 out
    {
        dim3 g(DIM / 256, MTOT / 128, 1);
        gemm_mma<3, 2><<<g, 256, SMEM>>>(xp0, xp1, wqt0, wqt1,
                                         nullptr, qp0, qp1, DIM, DIM, 0, 0, 0);
        gemm_mma<3, 2><<<g, 256, SMEM>>>(xp0, xp1, wkt0, wkt1,
                                         nullptr, kp0, kp1, DIM, DIM, 0, 0, 0);
        gemm_mma<3, 2><<<g, 256, SMEM>>>(xp0, xp1, wvt0, wvt1,
                                         nullptr, vp0, vp1, DIM, DIM, 0, 0, 0);
    }

    // 3) V transpose (per batch, both parts)
    {
        dim3 g(SEQ / 32, DIM / 32, BATCH * 2), blk(32, 8);
        vtrans_kernel<<<g, blk>>>(vp0, vp1, vtp0, vtp1);
    }

    // 4) scores S[b] = Q[b] @ K[b]^T, 3 combos ({11} negligible), fp32 out
    {
        dim3 g(SEQ / 256, SEQ / 128, BATCH);
        gemm_mma<3, 0><<<g, 256, SMEM>>>(qp0, qp1, kp0, kp1,
                                         S, nullptr, nullptr,
                                         DIM, SEQ,
                                         (size_t)SEQ * DIM, (size_t)SEQ * DIM,
                                         (size_t)SEQ * SEQ);
    }

    // 5) softmax -> P parts (2-split bf16)
    softmax_kernel<<<BATCH * SEQ, 256>>>(S, pp0, pp1);

    // 6) O[b] = P[b] @ Vt[b]^T, 3 combos, fp32 out
    {
        dim3 g(DIM / 256, SEQ / 128, BATCH);
        gemm_mma<3, 0><<<g, 256, SMEM>>>(pp0, pp1, vtp0, vtp1,
                                         out, nullptr, nullptr,
                                         SEQ, DIM,
                                         (size_t)SEQ * SEQ, (size_t)DIM * SEQ,
                                         (size_t)SEQ * DIM);
    }
}

// round 5
// speedup vs baseline: 3.2195x; 1.3663x over previous
#include <cuda_runtime.h>
#include <cuda_fp16.h>
#include <cstdint>

// ---------------------------------------------------------------------------
// SelfAttention B=4, S=2048, D=1024 fp32.
// mma.sync.m16n8k16 fp16 + ldmatrix + cp.async 3-stage pipeline.
// Precision plan (rel-err budget 1e-3):
//   Q/K proj:  2-split fp16 x / W, 3 combos -> ~1e-7
//   scores:    2-split fp16 Q/K, 3 combos  -> ~1e-6 logit err
//   V proj:    single fp16, 1 combo        -> ~2e-4
//   P, V:      stored single fp16          -> ~1.4e-4 each
//   AV:        1 combo
// fp32 accumulate everywhere. Expected total rel err ~3e-4.
// ---------------------------------------------------------------------------

#define BATCH 4
#define SEQ   2048
#define DIM   1024
#define MTOT  (BATCH * SEQ)   // 8192

#define AL __align__(128)
__device__ AL __half g_xp0[(size_t)MTOT * DIM];
__device__ AL __half g_xp1[(size_t)MTOT * DIM];
__device__ AL __half g_wqt0[(size_t)DIM * DIM];
__device__ AL __half g_wqt1[(size_t)DIM * DIM];
__device__ AL __half g_wkt0[(size_t)DIM * DIM];
__device__ AL __half g_wkt1[(size_t)DIM * DIM];
__device__ AL __half g_wvt0[(size_t)DIM * DIM];
__device__ AL __half g_qp0[(size_t)MTOT * DIM];
__device__ AL __half g_qp1[(size_t)MTOT * DIM];
__device__ AL __half g_kp0[(size_t)MTOT * DIM];
__device__ AL __half g_kp1[(size_t)MTOT * DIM];
__device__ AL __half g_vp[(size_t)MTOT * DIM];
__device__ AL __half g_vt[(size_t)BATCH * DIM * SEQ];
__device__ AL float  g_S[(size_t)BATCH * SEQ * SEQ];
__device__ AL __half g_pp[(size_t)BATCH * SEQ * SEQ];

// ---------------- PTX helpers ------------------------------------------------
__device__ __forceinline__ uint32_t smem_to_u32(const void* p) {
    uint32_t a;
    asm("{ .reg .u64 t; cvta.to.shared.u64 t, %1; cvt.u32.u64 %0, t; }"
        : "=r"(a) : "l"(p));
    return a;
}
#define CP_ASYNC_16(dst, src) \
    asm volatile("cp.async.cg.shared.global [%0], [%1], 16;" \
                 :: "r"(dst), "l"(src) : "memory")
#define CP_COMMIT() asm volatile("cp.async.commit_group;" ::: "memory")
#define CP_WAIT_1() asm volatile("cp.async.wait_group 1;" ::: "memory")

#define LDSM4(r0, r1, r2, r3, addr) \
    asm volatile("ldmatrix.sync.aligned.m8n8.x4.shared.b16 {%0,%1,%2,%3}, [%4];" \
                 : "=r"(r0), "=r"(r1), "=r"(r2), "=r"(r3) : "r"(addr))

#define MMA16816(d, a, b0r, b1r) \
    asm volatile("mma.sync.aligned.m16n8k16.row.col.f32.f16.f16.f32 " \
                 "{%0,%1,%2,%3}, {%4,%5,%6,%7}, {%8,%9}, {%0,%1,%2,%3};" \
                 : "+f"((d)[0]), "+f"((d)[1]), "+f"((d)[2]), "+f"((d)[3]) \
                 : "r"((a)[0]), "r"((a)[1]), "r"((a)[2]), "r"((a)[3]), \
                   "r"(b0r), "r"(b1r))

// ---------------- split helpers ----------------------------------------------
__device__ __forceinline__ uint32_t packh2(__half a, __half b) {
    return (uint32_t)__half_as_ushort(a) | ((uint32_t)__half_as_ushort(b) << 16);
}
__device__ __forceinline__ void split2h(float v, __half& h0, __half& h1) {
    h0 = __float2half_rn(v);
    h1 = __float2half_rn(v - __half2float(h0));
}

// ---------------- GEMM: C[M,N] = sum_cb A_part[CIA] * B_part[CIB]^T -----------
// A parts: M x K row-major (K-major). B parts: N x K row-major (K-major).
// CTA tile 128x256, BK=32, 8 warps (2 M x 4 N), warp tile 64x64.
// 3-stage cp.async ring, one __syncthreads per chunk.
// NA: number of parts per operand (1 or 2). NCOMBO: 1 or 3 ({00,01,10}).
// EPI: 0 = fp32 -> cf;  2 = 2-split fp16 -> c0,c1;  3 = single fp16 -> c0.
template <int NA, int NCOMBO, int EPI>
__global__ void __launch_bounds__(256, 1)
gemm_mma(const __half* __restrict__ a0, const __half* __restrict__ a1,
         const __half* __restrict__ b0, const __half* __restrict__ b1,
         float* __restrict__ cf,
         __half* __restrict__ c0, __half* __restrict__ c1,
         int Ktot, int ldC, size_t strideA, size_t strideB, size_t strideC)
{
    constexpr int CIA[3] = {0, 0, 1};
    constexpr int CIB[3] = {0, 1, 0};
    constexpr uint32_t A_SZ = 8192u;            // 128 x 32 fp16
    constexpr uint32_t B_SZ = 16384u;           // 256 x 32 fp16
    constexpr uint32_t B_OFF = NA * A_SZ;
    constexpr uint32_t STG = NA * (A_SZ + B_SZ);

    extern __shared__ char dsm[];
    const uint32_t sbase = smem_to_u32(dsm);

    const int tid  = threadIdx.x;
    const int wid  = tid >> 5;
    const int lane = tid & 31;
    const int lrow = lane & 15;
    const int lch  = lane >> 4;

    const int wm = (wid & 1) * 64;    // warp M offset
    const int wn = (wid >> 1) * 64;   // warp N offset

    const int mBase = blockIdx.y * 128;
    const int nBase = blockIdx.x * 256;

    const size_t zA = (size_t)blockIdx.z * strideA;
    const size_t zB = (size_t)blockIdx.z * strideB;
    const size_t zC = (size_t)blockIdx.z * strideC;
    const __half* ap[2] = { a0 + zA, (NA == 2) ? a1 + zA : a0 + zA };
    const __half* bp[2] = { b0 + zB, (NA == 2) ? b1 + zB : b0 + zB };

    const int arsw = ((wm + lrow) >> 1) & 3;
    const int brsw = ((wn + lrow) >> 1) & 3;
    const uint32_t aoff = (uint32_t)(wm + lrow) * 64;
    const uint32_t boff = (uint32_t)(wn + lrow) * 64;

    float acc[4][8][4];
#pragma unroll
    for (int i = 0; i < 4; i++)
#pragma unroll
        for (int j = 0; j < 8; j++)
#pragma unroll
            for (int e = 0; e < 4; e++) acc[i][j][e] = 0.0f;

    const int NCHUNK = Ktot >> 5;

    auto load_stage = [&](int chunk, int buf) {
        const int k0 = chunk << 5;
        const uint32_t sb = sbase + (uint32_t)buf * STG;
#pragma unroll
        for (int t = 0; t < NA; ++t) {
            const uint32_t tb = sb + (uint32_t)t * A_SZ;
#pragma unroll
            for (int i = 0; i < 2; ++i) {
                const int id  = tid + i * 256;      // 0..511
                const int row = id >> 2;
                const int c   = id & 3;
                const __half* g = ap[t] + (size_t)(mBase + row) * Ktot + k0 + c * 8;
                const uint32_t d = tb + (uint32_t)row * 64u +
                                   (uint32_t)((c ^ ((row >> 1) & 3)) * 16);
                CP_ASYNC_16(d, g);
            }
        }
#pragma unroll
        for (int t = 0; t < NA; ++t) {
            const uint32_t tb = sb + B_OFF + (uint32_t)t * B_SZ;
#pragma unroll
            for (int i = 0; i < 4; ++i) {
                const int id  = tid + i * 256;      // 0..1023
                const int row = id >> 2;
                const int c   = id & 3;
                const __half* g = bp[t] + (size_t)(nBase + row) * Ktot + k0 + c * 8;
                const uint32_t d = tb + (uint32_t)row * 64u +
                                   (uint32_t)((c ^ ((row >> 1) & 3)) * 16);
                CP_ASYNC_16(d, g);
            }
        }
    };

    load_stage(0, 0); CP_COMMIT();
    load_stage(1, 1); CP_COMMIT();

    int buf = 0;
    for (int chunk = 0; chunk < NCHUNK; ++chunk) {
        CP_WAIT_1();
        __syncthreads();

        const uint32_t stb = sbase + (uint32_t)buf * STG;
#pragma unroll
        for (int cb = 0; cb < NCOMBO; ++cb) {
            const uint32_t abase = stb + (uint32_t)CIA[cb] * A_SZ + aoff;
            const uint32_t bbase = stb + B_OFF + (uint32_t)CIB[cb] * B_SZ + boff;
#pragma unroll
            for (int k16 = 0; k16 < 2; ++k16) {
                const uint32_t asw = (uint32_t)(((k16 * 2 + lch) ^ arsw) * 16);
                const uint32_t bsw = (uint32_t)(((k16 * 2 + lch) ^ brsw) * 16);
                uint32_t afr[4][4];
#pragma unroll
                for (int im = 0; im < 4; ++im)
                    LDSM4(afr[im][0], afr[im][1], afr[im][2], afr[im][3],
                          abase + (uint32_t)im * 1024u + asw);
                uint32_t bfr[4][4];
#pragma unroll
                for (int g = 0; g < 4; ++g)
                    LDSM4(bfr[g][0], bfr[g][1], bfr[g][2], bfr[g][3],
                          bbase + (uint32_t)g * 1024u + bsw);
#pragma unroll
                for (int im = 0; im < 4; ++im)
#pragma unroll
                    for (int in = 0; in < 8; ++in)
                        MMA16816(acc[im][in], afr[im],
                                 bfr[in >> 1][in & 1], bfr[in >> 1][(in & 1) + 2]);
            }
        }
        if (chunk + 2 < NCHUNK) {
            int nb = buf + 2; if (nb >= 3) nb -= 3;
            load_stage(chunk + 2, nb);
        }
        CP_COMMIT();   // keep group counts aligned with wait_group(1)
        if (++buf == 3) buf = 0;
    }

    // ---------------- epilogue ----------------
    const int quad = lane >> 2;       // 0..7
    const int tcol = lane & 3;        // 0..3
#pragma unroll
    for (int im = 0; im < 4; ++im) {
#pragma unroll
        for (int in = 0; in < 8; ++in) {
            const int row = mBase + wm + im * 16 + quad;
            const int col = nBase + wn + in * 8 + tcol * 2;
            const size_t olo = zC + (size_t)row * ldC + col;
            const size_t ohi = zC + (size_t)(row + 8) * ldC + col;
            if constexpr (EPI == 0) {
                *reinterpret_cast<float2*>(cf + olo) =
                    make_float2(acc[im][in][0], acc[im][in][1]);
                *reinterpret_cast<float2*>(cf + ohi) =
                    make_float2(acc[im][in][2], acc[im][in][3]);
            } else if constexpr (EPI == 2) {
                __half xh, xl, yh, yl;
                split2h(acc[im][in][0], xh, xl); split2h(acc[im][in][1], yh, yl);
                *reinterpret_cast<uint32_t*>(c0 + olo) = packh2(xh, yh);
                *reinterpret_cast<uint32_t*>(c1 + olo) = packh2(xl, yl);
                split2h(acc[im][in][2], xh, xl); split2h(acc[im][in][3], yh, yl);
                *reinterpret_cast<uint32_t*>(c0 + ohi) = packh2(xh, yh);
                *reinterpret_cast<uint32_t*>(c1 + ohi) = packh2(xl, yl);
            } else {
                __half2 lo = __floats2half2_rn(acc[im][in][0], acc[im][in][1]);
                __half2 hi = __floats2half2_rn(acc[im][in][2], acc[im][in][3]);
                *reinterpret_cast<__half2*>(c0 + olo) = lo;
                *reinterpret_cast<__half2*>(c0 + ohi) = hi;
            }
        }
    }
}

// ---------------- aux kernels --------------------------------------------------
__global__ void __launch_bounds__(256)
split2_kernel(const float* __restrict__ src, __half* __restrict__ d0,
              __half* __restrict__ d1)
{
    const size_t i = (size_t)blockIdx.x * 256 + threadIdx.x;
    const float4 v = reinterpret_cast<const float4*>(src)[i];
    __half a0, a1, b0, b1, c0, c1, e0, e1;
    split2h(v.x, a0, a1); split2h(v.y, b0, b1);
    split2h(v.z, c0, c1); split2h(v.w, e0, e1);
    reinterpret_cast<uint2*>(d0)[i] = make_uint2(packh2(a0, b0), packh2(c0, e0));
    reinterpret_cast<uint2*>(d1)[i] = make_uint2(packh2(a1, b1), packh2(c1, e1));
}

// W [K,N] fp32 -> transposed 2-way split Wt parts [N,K] fp16
__global__ void __launch_bounds__(256)
wsplit_kernel(const float* __restrict__ W, __half* __restrict__ t0,
              __half* __restrict__ t1)
{
    __shared__ float tile[32][33];
    const int tx = threadIdx.x, ty = threadIdx.y;
    const int k0 = blockIdx.y * 32, n0 = blockIdx.x * 32;
#pragma unroll
    for (int i = 0; i < 4; ++i)
        tile[ty + i * 8][tx] = W[(size_t)(k0 + ty + i * 8) * DIM + n0 + tx];
    __syncthreads();
#pragma unroll
    for (int i = 0; i < 4; ++i) {
        const int n = n0 + ty + i * 8;
        const float v = tile[tx][ty + i * 8];
        __half h0, h1;
        split2h(v, h0, h1);
        t0[(size_t)n * DIM + k0 + tx] = h0;
        if (t1) t1[(size_t)n * DIM + k0 + tx] = h1;
    }
}

// V [B*S, D] fp16 -> Vt [B][D][S] fp16
__global__ void __launch_bounds__(256)
vtrans_kernel(const __half* __restrict__ v, __half* __restrict__ t)
{
    __shared__ __half tile[32][33];
    const int b = blockIdx.z;
    const int tx = threadIdx.x, ty = threadIdx.y;
    const int s0 = blockIdx.x * 32, d0 = blockIdx.y * 32;
#pragma unroll
    for (int i = 0; i < 4; ++i)
        tile[ty + i * 8][tx] = v[((size_t)b * SEQ + s0 + ty + i * 8) * DIM + d0 + tx];
    __syncthreads();
#pragma unroll
    for (int i = 0; i < 4; ++i)
        t[(size_t)b * DIM * SEQ + (size_t)(d0 + ty + i * 8) * SEQ + s0 + tx] =
            tile[tx][ty + i * 8];
}

// row softmax of S (fp32, row length SEQ) -> single fp16 P
__global__ void __launch_bounds__(256)
softmax_kernel(const float* __restrict__ S, __half* __restrict__ p0)
{
    const float4* row = reinterpret_cast<const float4*>(S + (size_t)blockIdx.x * SEQ);
    const int tid = threadIdx.x;

    float4 a = row[tid];
    float4 b = row[tid + 256];

    float m = fmaxf(fmaxf(fmaxf(a.x, a.y), fmaxf(a.z, a.w)),
                    fmaxf(fmaxf(b.x, b.y), fmaxf(b.z, b.w)));
#pragma unroll
    for (int o = 16; o > 0; o >>= 1) m = fmaxf(m, __shfl_xor_sync(0xffffffffu, m, o));

    __shared__ float redmax[8];
    __shared__ float redsum[8];
    if ((tid & 31) == 0) redmax[tid >> 5] = m;
    __syncthreads();
    float mrow = redmax[0];
#pragma unroll
    for (int i = 1; i < 8; ++i) mrow = fmaxf(mrow, redmax[i]);

    a.x = __expf(a.x - mrow); a.y = __expf(a.y - mrow);
    a.z = __expf(a.z - mrow); a.w = __expf(a.w - mrow);
    b.x = __expf(b.x - mrow); b.y = __expf(b.y - mrow);
    b.z = __expf(b.z - mrow); b.w = __expf(b.w - mrow);

    float s = (a.x + a.y) + (a.z + a.w) + (b.x + b.y) + (b.z + b.w);
#pragma unroll
    for (int o = 16; o > 0; o >>= 1) s += __shfl_xor_sync(0xffffffffu, s, o);
    if ((tid & 31) == 0) redsum[tid >> 5] = s;
    __syncthreads();
    float srow = 0.0f;
#pragma unroll
    for (int i = 0; i < 8; ++i) srow += redsum[i];
    const float inv = 1.0f / srow;

    uint2* r0 = reinterpret_cast<uint2*>(p0 + (size_t)blockIdx.x * SEQ);
    r0[tid] = make_uint2(
        packh2(__float2half_rn(a.x * inv), __float2half_rn(a.y * inv)),
        packh2(__float2half_rn(a.z * inv), __float2half_rn(a.w * inv)));
    r0[tid + 256] = make_uint2(
        packh2(__float2half_rn(b.x * inv), __float2half_rn(b.y * inv)),
        packh2(__float2half_rn(b.z * inv), __float2half_rn(b.w * inv)));
}

// ---------------- launch --------------------------------------------------------
extern "C" void kernel_launch(void* const* d_in, const int* in_sizes, int n_in,
                              void* d_out, int out_size)
{
    const float* x  = (const float*)d_in[0];
    const float* Wq = (const float*)d_in[1];
    const float* Wk = (const float*)d_in[2];
    const float* Wv = (const float*)d_in[3];
    float* out = (float*)d_out;

    __half *xp0, *xp1, *wqt0, *wqt1, *wkt0, *wkt1, *wvt0;
    __half *qp0, *qp1, *kp0, *kp1, *vp, *vt, *pp;
    float* S;
    cudaGetSymbolAddress((void**)&xp0, g_xp0);   cudaGetSymbolAddress((void**)&xp1, g_xp1);
    cudaGetSymbolAddress((void**)&wqt0, g_wqt0); cudaGetSymbolAddress((void**)&wqt1, g_wqt1);
    cudaGetSymbolAddress((void**)&wkt0, g_wkt0); cudaGetSymbolAddress((void**)&wkt1, g_wkt1);
    cudaGetSymbolAddress((void**)&wvt0, g_wvt0);
    cudaGetSymbolAddress((void**)&qp0, g_qp0);   cudaGetSymbolAddress((void**)&qp1, g_qp1);
    cudaGetSymbolAddress((void**)&kp0, g_kp0);   cudaGetSymbolAddress((void**)&kp1, g_kp1);
    cudaGetSymbolAddress((void**)&vp, g_vp);     cudaGetSymbolAddress((void**)&vt, g_vt);
    cudaGetSymbolAddress((void**)&pp, g_pp);
    cudaGetSymbolAddress((void**)&S, g_S);

    const int SMEM2 = 3 * 49152;  // NA=2: 3 stages x 48KB = 147456
    const int SMEM1 = 3 * 24576;  // NA=1: 3 stages x 24KB = 73728
    cudaFuncSetAttribute(gemm_mma<2, 3, 2>, cudaFuncAttributeMaxDynamicSharedMemorySize, SMEM2);
    cudaFuncSetAttribute(gemm_mma<2, 3, 0>, cudaFuncAttributeMaxDynamicSharedMemorySize, SMEM2);
    cudaFuncSetAttribute(gemm_mma<1, 1, 3>, cudaFuncAttributeMaxDynamicSharedMemorySize, SMEM1);
    cudaFuncSetAttribute(gemm_mma<1, 1, 0>, cudaFuncAttributeMaxDynamicSharedMemorySize, SMEM1);

    // 1) operand splits
    split2_kernel<<<(MTOT * DIM) / 1024, 256>>>(x, xp0, xp1);
    {
        dim3 g(DIM / 32, DIM / 32), blk(32, 8);
        wsplit_kernel<<<g, blk>>>(Wq, wqt0, wqt1);
        wsplit_kernel<<<g, blk>>>(Wk, wkt0, wkt1);
        wsplit_kernel<<<g, blk>>>(Wv, wvt0, nullptr);
    }

    // 2) projections
    {
        dim3 g(DIM / 256, MTOT / 128, 1);
        gemm_mma<2, 3, 2><<<g, 256, SMEM2>>>(xp0, xp1, wqt0, wqt1,
                                             nullptr, qp0, qp1, DIM, DIM, 0, 0, 0);
        gemm_mma<2, 3, 2><<<g, 256, SMEM2>>>(xp0, xp1, wkt0, wkt1,
                                             nullptr, kp0, kp1, DIM, DIM, 0, 0, 0);
        gemm_mma<1, 1, 3><<<g, 256, SMEM1>>>(xp0, nullptr, wvt0, nullptr,
                                             nullptr, vp, nullptr, DIM, DIM, 0, 0, 0);
    }

    // 3) V transpose (per batch)
    {
        dim3 g(SEQ / 32, DIM / 32, BATCH), blk(32, 8);
        vtrans_kernel<<<g, blk>>>(vp, vt);
    }

    // 4) scores S[b] = Q[b] @ K[b]^T, 3 combos, fp32 out
    {
        dim3 g(SEQ / 256, SEQ / 128, BATCH);
        gemm_mma<2, 3, 0><<<g, 256, SMEM2>>>(qp0, qp1, kp0, kp1,
                                             S, nullptr, nullptr,
                                             DIM, SEQ,
                                             (size_t)SEQ * DIM, (size_t)SEQ * DIM,
                                             (size_t)SEQ * SEQ);
    }

    // 5) softmax -> P (single fp16)
    softmax_kernel<<<BATCH * SEQ, 256>>>(S, pp);

    // 6) O[b] = P[b] @ Vt[b]^T, 1 combo, fp32 out
    {
        dim3 g(DIM / 256, SEQ / 128, BATCH);
        gemm_mma<1, 1, 0><<<g, 256, SMEM1>>>(pp, nullptr, vt, nullptr,
                                             out, nullptr, nullptr,
                                             SEQ, DIM,
                                             (size_t)SEQ * SEQ, (size_t)DIM * SEQ,
                                             (size_t)SEQ * DIM);
    }
}

// round 6
// speedup vs baseline: 3.4157x; 1.0610x over previous
#include <cuda_runtime.h>
#include <cuda_fp16.h>
#include <cstdint>

// ---------------------------------------------------------------------------
// SelfAttention B=4, S=2048, D=1024 fp32.
// mma.sync.m16n8k16 fp16 + ldmatrix + cp.async 3-stage pipeline.
// Precision plan (rel-err budget 1e-3):
//   Q/K proj:  2-split fp16 x / W, 3 combos
//   scores:    2-split fp16 Q/K, 3 combos
//   V proj:    single fp16, 1 combo; P, V single fp16; AV 1 combo
// fp32 accumulate everywhere. Measured rel err ~3.8e-4.
// R6: CTA 128x128, 4 warps (warp tile 64x64), 2 CTAs/SM for sync overlap.
// ---------------------------------------------------------------------------

#define BATCH 4
#define SEQ   2048
#define DIM   1024
#define MTOT  (BATCH * SEQ)   // 8192

#define AL __align__(128)
__device__ AL __half g_xp0[(size_t)MTOT * DIM];
__device__ AL __half g_xp1[(size_t)MTOT * DIM];
__device__ AL __half g_wqt0[(size_t)DIM * DIM];
__device__ AL __half g_wqt1[(size_t)DIM * DIM];
__device__ AL __half g_wkt0[(size_t)DIM * DIM];
__device__ AL __half g_wkt1[(size_t)DIM * DIM];
__device__ AL __half g_wvt0[(size_t)DIM * DIM];
__device__ AL __half g_qp0[(size_t)MTOT * DIM];
__device__ AL __half g_qp1[(size_t)MTOT * DIM];
__device__ AL __half g_kp0[(size_t)MTOT * DIM];
__device__ AL __half g_kp1[(size_t)MTOT * DIM];
__device__ AL __half g_vp[(size_t)MTOT * DIM];
__device__ AL __half g_vt[(size_t)BATCH * DIM * SEQ];
__device__ AL float  g_S[(size_t)BATCH * SEQ * SEQ];
__device__ AL __half g_pp[(size_t)BATCH * SEQ * SEQ];

// ---------------- PTX helpers ------------------------------------------------
__device__ __forceinline__ uint32_t smem_to_u32(const void* p) {
    uint32_t a;
    asm("{ .reg .u64 t; cvta.to.shared.u64 t, %1; cvt.u32.u64 %0, t; }"
        : "=r"(a) : "l"(p));
    return a;
}
#define CP_ASYNC_16(dst, src) \
    asm volatile("cp.async.cg.shared.global [%0], [%1], 16;" \
                 :: "r"(dst), "l"(src) : "memory")
#define CP_COMMIT() asm volatile("cp.async.commit_group;" ::: "memory")
#define CP_WAIT_1() asm volatile("cp.async.wait_group 1;" ::: "memory")

#define LDSM4(r0, r1, r2, r3, addr) \
    asm volatile("ldmatrix.sync.aligned.m8n8.x4.shared.b16 {%0,%1,%2,%3}, [%4];" \
                 : "=r"(r0), "=r"(r1), "=r"(r2), "=r"(r3) : "r"(addr))

#define MMA16816(d, a, b0r, b1r) \
    asm volatile("mma.sync.aligned.m16n8k16.row.col.f32.f16.f16.f32 " \
                 "{%0,%1,%2,%3}, {%4,%5,%6,%7}, {%8,%9}, {%0,%1,%2,%3};" \
                 : "+f"((d)[0]), "+f"((d)[1]), "+f"((d)[2]), "+f"((d)[3]) \
                 : "r"((a)[0]), "r"((a)[1]), "r"((a)[2]), "r"((a)[3]), \
                   "r"(b0r), "r"(b1r))

// ---------------- split helpers ----------------------------------------------
__device__ __forceinline__ uint32_t packh2(__half a, __half b) {
    return (uint32_t)__half_as_ushort(a) | ((uint32_t)__half_as_ushort(b) << 16);
}
__device__ __forceinline__ void split2h(float v, __half& h0, __half& h1) {
    h0 = __float2half_rn(v);
    h1 = __float2half_rn(v - __half2float(h0));
}

// ---------------- GEMM: C[M,N] = sum_cb A_part[CIA] * B_part[CIB]^T -----------
// A parts: M x K row-major (K-major). B parts: N x K row-major (K-major).
// CTA tile 128x128, BK=32, 4 warps (2 M x 2 N), warp tile 64x64.
// 3-stage cp.async ring, one __syncthreads per chunk, 2 CTAs/SM.
// NA: parts per operand (1 or 2). NCOMBO: 1 or 3 ({00,01,10}).
// EPI: 0 = fp32 -> cf;  2 = 2-split fp16 -> c0,c1;  3 = single fp16 -> c0.
template <int NA, int NCOMBO, int EPI>
__global__ void __launch_bounds__(128, 2)
gemm_mma(const __half* __restrict__ a0, const __half* __restrict__ a1,
         const __half* __restrict__ b0, const __half* __restrict__ b1,
         float* __restrict__ cf,
         __half* __restrict__ c0, __half* __restrict__ c1,
         int Ktot, int ldC, size_t strideA, size_t strideB, size_t strideC)
{
    constexpr int CIA[3] = {0, 0, 1};
    constexpr int CIB[3] = {0, 1, 0};
    constexpr uint32_t A_SZ = 8192u;            // 128 x 32 fp16
    constexpr uint32_t B_SZ = 8192u;            // 128 x 32 fp16
    constexpr uint32_t B_OFF = NA * A_SZ;
    constexpr uint32_t STG = NA * (A_SZ + B_SZ);

    extern __shared__ char dsm[];
    const uint32_t sbase = smem_to_u32(dsm);

    const int tid  = threadIdx.x;
    const int wid  = tid >> 5;
    const int lane = tid & 31;
    const int lrow = lane & 15;
    const int lch  = lane >> 4;

    const int wm = (wid & 1) * 64;    // warp M offset
    const int wn = (wid >> 1) * 64;   // warp N offset

    const int mBase = blockIdx.y * 128;
    const int nBase = blockIdx.x * 128;

    const size_t zA = (size_t)blockIdx.z * strideA;
    const size_t zB = (size_t)blockIdx.z * strideB;
    const size_t zC = (size_t)blockIdx.z * strideC;
    const __half* ap[2] = { a0 + zA, (NA == 2) ? a1 + zA : a0 + zA };
    const __half* bp[2] = { b0 + zB, (NA == 2) ? b1 + zB : b0 + zB };

    const int arsw = ((wm + lrow) >> 1) & 3;
    const int brsw = ((wn + lrow) >> 1) & 3;
    const uint32_t aoff = (uint32_t)(wm + lrow) * 64;
    const uint32_t boff = (uint32_t)(wn + lrow) * 64;

    float acc[4][8][4];
#pragma unroll
    for (int i = 0; i < 4; i++)
#pragma unroll
        for (int j = 0; j < 8; j++)
#pragma unroll
            for (int e = 0; e < 4; e++) acc[i][j][e] = 0.0f;

    const int NCHUNK = Ktot >> 5;

    auto load_stage = [&](int chunk, int buf) {
        const int k0 = chunk << 5;
        const uint32_t sb = sbase + (uint32_t)buf * STG;
#pragma unroll
        for (int t = 0; t < NA; ++t) {
            const uint32_t tb = sb + (uint32_t)t * A_SZ;
#pragma unroll
            for (int i = 0; i < 4; ++i) {
                const int id  = tid + i * 128;      // 0..511
                const int row = id >> 2;
                const int c   = id & 3;
                const __half* g = ap[t] + (size_t)(mBase + row) * Ktot + k0 + c * 8;
                const uint32_t d = tb + (uint32_t)row * 64u +
                                   (uint32_t)((c ^ ((row >> 1) & 3)) * 16);
                CP_ASYNC_16(d, g);
            }
        }
#pragma unroll
        for (int t = 0; t < NA; ++t) {
            const uint32_t tb = sb + B_OFF + (uint32_t)t * B_SZ;
#pragma unroll
            for (int i = 0; i < 4; ++i) {
                const int id  = tid + i * 128;      // 0..511
                const int row = id >> 2;
                const int c   = id & 3;
                const __half* g = bp[t] + (size_t)(nBase + row) * Ktot + k0 + c * 8;
                const uint32_t d = tb + (uint32_t)row * 64u +
                                   (uint32_t)((c ^ ((row >> 1) & 3)) * 16);
                CP_ASYNC_16(d, g);
            }
        }
    };

    load_stage(0, 0); CP_COMMIT();
    load_stage(1, 1); CP_COMMIT();

    int buf = 0;
    for (int chunk = 0; chunk < NCHUNK; ++chunk) {
        CP_WAIT_1();
        __syncthreads();

        const uint32_t stb = sbase + (uint32_t)buf * STG;
#pragma unroll
        for (int cb = 0; cb < NCOMBO; ++cb) {
            const uint32_t abase = stb + (uint32_t)CIA[cb] * A_SZ + aoff;
            const uint32_t bbase = stb + B_OFF + (uint32_t)CIB[cb] * B_SZ + boff;
#pragma unroll
            for (int k16 = 0; k16 < 2; ++k16) {
                const uint32_t asw = (uint32_t)(((k16 * 2 + lch) ^ arsw) * 16);
                const uint32_t bsw = (uint32_t)(((k16 * 2 + lch) ^ brsw) * 16);
                uint32_t afr[4][4];
#pragma unroll
                for (int im = 0; im < 4; ++im)
                    LDSM4(afr[im][0], afr[im][1], afr[im][2], afr[im][3],
                          abase + (uint32_t)im * 1024u + asw);
                uint32_t bfr[4][4];
#pragma unroll
                for (int g = 0; g < 4; ++g)
                    LDSM4(bfr[g][0], bfr[g][1], bfr[g][2], bfr[g][3],
                          bbase + (uint32_t)g * 1024u + bsw);
#pragma unroll
                for (int im = 0; im < 4; ++im)
#pragma unroll
                    for (int in = 0; in < 8; ++in)
                        MMA16816(acc[im][in], afr[im],
                                 bfr[in >> 1][in & 1], bfr[in >> 1][(in & 1) + 2]);
            }
        }
        if (chunk + 2 < NCHUNK) {
            int nb = buf + 2; if (nb >= 3) nb -= 3;
            load_stage(chunk + 2, nb);
        }
        CP_COMMIT();   // keep group counts aligned with wait_group(1)
        if (++buf == 3) buf = 0;
    }

    // ---------------- epilogue ----------------
    const int quad = lane >> 2;       // 0..7
    const int tcol = lane & 3;        // 0..3
#pragma unroll
    for (int im = 0; im < 4; ++im) {
#pragma unroll
        for (int in = 0; in < 8; ++in) {
            const int row = mBase + wm + im * 16 + quad;
            const int col = nBase + wn + in * 8 + tcol * 2;
            const size_t olo = zC + (size_t)row * ldC + col;
            const size_t ohi = zC + (size_t)(row + 8) * ldC + col;
            if constexpr (EPI == 0) {
                *reinterpret_cast<float2*>(cf + olo) =
                    make_float2(acc[im][in][0], acc[im][in][1]);
                *reinterpret_cast<float2*>(cf + ohi) =
                    make_float2(acc[im][in][2], acc[im][in][3]);
            } else if constexpr (EPI == 2) {
                __half xh, xl, yh, yl;
                split2h(acc[im][in][0], xh, xl); split2h(acc[im][in][1], yh, yl);
                *reinterpret_cast<uint32_t*>(c0 + olo) = packh2(xh, yh);
                *reinterpret_cast<uint32_t*>(c1 + olo) = packh2(xl, yl);
                split2h(acc[im][in][2], xh, xl); split2h(acc[im][in][3], yh, yl);
                *reinterpret_cast<uint32_t*>(c0 + ohi) = packh2(xh, yh);
                *reinterpret_cast<uint32_t*>(c1 + ohi) = packh2(xl, yl);
            } else {
                __half2 lo = __floats2half2_rn(acc[im][in][0], acc[im][in][1]);
                __half2 hi = __floats2half2_rn(acc[im][in][2], acc[im][in][3]);
                *reinterpret_cast<__half2*>(c0 + olo) = lo;
                *reinterpret_cast<__half2*>(c0 + ohi) = hi;
            }
        }
    }
}

// ---------------- aux kernels --------------------------------------------------
__global__ void __launch_bounds__(256)
split2_kernel(const float* __restrict__ src, __half* __restrict__ d0,
              __half* __restrict__ d1)
{
    const size_t i = (size_t)blockIdx.x * 256 + threadIdx.x;
    const float4 v = reinterpret_cast<const float4*>(src)[i];
    __half a0, a1, b0, b1, c0, c1, e0, e1;
    split2h(v.x, a0, a1); split2h(v.y, b0, b1);
    split2h(v.z, c0, c1); split2h(v.w, e0, e1);
    reinterpret_cast<uint2*>(d0)[i] = make_uint2(packh2(a0, b0), packh2(c0, e0));
    reinterpret_cast<uint2*>(d1)[i] = make_uint2(packh2(a1, b1), packh2(c1, e1));
}

// W [K,N] fp32 -> transposed 2-way split Wt parts [N,K] fp16
__global__ void __launch_bounds__(256)
wsplit_kernel(const float* __restrict__ W, __half* __restrict__ t0,
              __half* __restrict__ t1)
{
    __shared__ float tile[32][33];
    const int tx = threadIdx.x, ty = threadIdx.y;
    const int k0 = blockIdx.y * 32, n0 = blockIdx.x * 32;
#pragma unroll
    for (int i = 0; i < 4; ++i)
        tile[ty + i * 8][tx] = W[(size_t)(k0 + ty + i * 8) * DIM + n0 + tx];
    __syncthreads();
#pragma unroll
    for (int i = 0; i < 4; ++i) {
        const int n = n0 + ty + i * 8;
        const float v = tile[tx][ty + i * 8];
        __half h0, h1;
        split2h(v, h0, h1);
        t0[(size_t)n * DIM + k0 + tx] = h0;
        if (t1) t1[(size_t)n * DIM + k0 + tx] = h1;
    }
}

// V [B*S, D] fp16 -> Vt [B][D][S] fp16
__global__ void __launch_bounds__(256)
vtrans_kernel(const __half* __restrict__ v, __half* __restrict__ t)
{
    __shared__ __half tile[32][33];
    const int b = blockIdx.z;
    const int tx = threadIdx.x, ty = threadIdx.y;
    const int s0 = blockIdx.x * 32, d0 = blockIdx.y * 32;
#pragma unroll
    for (int i = 0; i < 4; ++i)
        tile[ty + i * 8][tx] = v[((size_t)b * SEQ + s0 + ty + i * 8) * DIM + d0 + tx];
    __syncthreads();
#pragma unroll
    for (int i = 0; i < 4; ++i)
        t[(size_t)b * DIM * SEQ + (size_t)(d0 + ty + i * 8) * SEQ + s0 + tx] =
            tile[tx][ty + i * 8];
}

// row softmax of S (fp32, row length SEQ) -> single fp16 P
__global__ void __launch_bounds__(256)
softmax_kernel(const float* __restrict__ S, __half* __restrict__ p0)
{
    const float4* row = reinterpret_cast<const float4*>(S + (size_t)blockIdx.x * SEQ);
    const int tid = threadIdx.x;

    float4 a = row[tid];
    float4 b = row[tid + 256];

    float m = fmaxf(fmaxf(fmaxf(a.x, a.y), fmaxf(a.z, a.w)),
                    fmaxf(fmaxf(b.x, b.y), fmaxf(b.z, b.w)));
#pragma unroll
    for (int o = 16; o > 0; o >>= 1) m = fmaxf(m, __shfl_xor_sync(0xffffffffu, m, o));

    __shared__ float redmax[8];
    __shared__ float redsum[8];
    if ((tid & 31) == 0) redmax[tid >> 5] = m;
    __syncthreads();
    float mrow = redmax[0];
#pragma unroll
    for (int i = 1; i < 8; ++i) mrow = fmaxf(mrow, redmax[i]);

    a.x = __expf(a.x - mrow); a.y = __expf(a.y - mrow);
    a.z = __expf(a.z - mrow); a.w = __expf(a.w - mrow);
    b.x = __expf(b.x - mrow); b.y = __expf(b.y - mrow);
    b.z = __expf(b.z - mrow); b.w = __expf(b.w - mrow);

    float s = (a.x + a.y) + (a.z + a.w) + (b.x + b.y) + (b.z + b.w);
#pragma unroll
    for (int o = 16; o > 0; o >>= 1) s += __shfl_xor_sync(0xffffffffu, s, o);
    if ((tid & 31) == 0) redsum[tid >> 5] = s;
    __syncthreads();
    float srow = 0.0f;
#pragma unroll
    for (int i = 0; i < 8; ++i) srow += redsum[i];
    const float inv = 1.0f / srow;

    uint2* r0 = reinterpret_cast<uint2*>(p0 + (size_t)blockIdx.x * SEQ);
    r0[tid] = make_uint2(
        packh2(__float2half_rn(a.x * inv), __float2half_rn(a.y * inv)),
        packh2(__float2half_rn(a.z * inv), __float2half_rn(a.w * inv)));
    r0[tid + 256] = make_uint2(
        packh2(__float2half_rn(b.x * inv), __float2half_rn(b.y * inv)),
        packh2(__float2half_rn(b.z * inv), __float2half_rn(b.w * inv)));
}

// ---------------- launch --------------------------------------------------------
extern "C" void kernel_launch(void* const* d_in, const int* in_sizes, int n_in,
                              void* d_out, int out_size)
{
    const float* x  = (const float*)d_in[0];
    const float* Wq = (const float*)d_in[1];
    const float* Wk = (const float*)d_in[2];
    const float* Wv = (const float*)d_in[3];
    float* out = (float*)d_out;

    __half *xp0, *xp1, *wqt0, *wqt1, *wkt0, *wkt1, *wvt0;
    __half *qp0, *qp1, *kp0, *kp1, *vp, *vt, *pp;
    float* S;
    cudaGetSymbolAddress((void**)&xp0, g_xp0);   cudaGetSymbolAddress((void**)&xp1, g_xp1);
    cudaGetSymbolAddress((void**)&wqt0, g_wqt0); cudaGetSymbolAddress((void**)&wqt1, g_wqt1);
    cudaGetSymbolAddress((void**)&wkt0, g_wkt0); cudaGetSymbolAddress((void**)&wkt1, g_wkt1);
    cudaGetSymbolAddress((void**)&wvt0, g_wvt0);
    cudaGetSymbolAddress((void**)&qp0, g_qp0);   cudaGetSymbolAddress((void**)&qp1, g_qp1);
    cudaGetSymbolAddress((void**)&kp0, g_kp0);   cudaGetSymbolAddress((void**)&kp1, g_kp1);
    cudaGetSymbolAddress((void**)&vp, g_vp);     cudaGetSymbolAddress((void**)&vt, g_vt);
    cudaGetSymbolAddress((void**)&pp, g_pp);
    cudaGetSymbolAddress((void**)&S, g_S);

    const int SMEM2 = 3 * 32768;  // NA=2: 3 stages x 32KB = 98304 (2 CTAs/SM)
    const int SMEM1 = 3 * 16384;  // NA=1: 3 stages x 16KB = 49152
    cudaFuncSetAttribute(gemm_mma<2, 3, 2>, cudaFuncAttributeMaxDynamicSharedMemorySize, SMEM2);
    cudaFuncSetAttribute(gemm_mma<2, 3, 0>, cudaFuncAttributeMaxDynamicSharedMemorySize, SMEM2);
    cudaFuncSetAttribute(gemm_mma<1, 1, 3>, cudaFuncAttributeMaxDynamicSharedMemorySize, SMEM1);
    cudaFuncSetAttribute(gemm_mma<1, 1, 0>, cudaFuncAttributeMaxDynamicSharedMemorySize, SMEM1);

    // 1) operand splits
    split2_kernel<<<(MTOT * DIM) / 1024, 256>>>(x, xp0, xp1);
    {
        dim3 g(DIM / 32, DIM / 32), blk(32, 8);
        wsplit_kernel<<<g, blk>>>(Wq, wqt0, wqt1);
        wsplit_kernel<<<g, blk>>>(Wk, wkt0, wkt1);
        wsplit_kernel<<<g, blk>>>(Wv, wvt0, nullptr);
    }

    // 2) projections
    {
        dim3 g(DIM / 128, MTOT / 128, 1);
        gemm_mma<2, 3, 2><<<g, 128, SMEM2>>>(xp0, xp1, wqt0, wqt1,
                                             nullptr, qp0, qp1, DIM, DIM, 0, 0, 0);
        gemm_mma<2, 3, 2><<<g, 128, SMEM2>>>(xp0, xp1, wkt0, wkt1,
                                             nullptr, kp0, kp1, DIM, DIM, 0, 0, 0);
        gemm_mma<1, 1, 3><<<g, 128, SMEM1>>>(xp0, nullptr, wvt0, nullptr,
                                             nullptr, vp, nullptr, DIM, DIM, 0, 0, 0);
    }

    // 3) V transpose (per batch)
    {
        dim3 g(SEQ / 32, DIM / 32, BATCH), blk(32, 8);
        vtrans_kernel<<<g, blk>>>(vp, vt);
    }

    // 4) scores S[b] = Q[b] @ K[b]^T, 3 combos, fp32 out
    {
        dim3 g(SEQ / 128, SEQ / 128, BATCH);
        gemm_mma<2, 3, 0><<<g, 128, SMEM2>>>(qp0, qp1, kp0, kp1,
                                             S, nullptr, nullptr,
                                             DIM, SEQ,
                                             (size_t)SEQ * DIM, (size_t)SEQ * DIM,
                                             (size_t)SEQ * SEQ);
    }

    // 5) softmax -> P (single fp16)
    softmax_kernel<<<BATCH * SEQ, 256>>>(S, pp);

    // 6) O[b] = P[b] @ Vt[b]^T, 1 combo, fp32 out
    {
        dim3 g(DIM / 128, SEQ / 128, BATCH);
        gemm_mma<1, 1, 0><<<g, 128, SMEM1>>>(pp, nullptr, vt, nullptr,
                                             out, nullptr, nullptr,
                                             SEQ, DIM,
                                             (size_t)SEQ * SEQ, (size_t)DIM * SEQ,
                                             (size_t)SEQ * DIM);
    }
}

// round 7
// speedup vs baseline: 3.4708x; 1.0161x over previous
#include <cuda_runtime.h>
#include <cuda_fp16.h>
#include <cstdint>

// ---------------------------------------------------------------------------
// SelfAttention B=4, S=2048, D=1024 fp32.
// mma.sync.m16n8k16 fp16 + ldmatrix + cp.async 3-stage pipeline.
// Precision plan (rel-err budget 1e-3):
//   Q/K proj:  2-split fp16 x / W, 3 combos
//   scores:    2-split fp16 Q/K, 3 combos
//   V proj:    single fp16, 1 combo; P, V single fp16; AV 1 combo
// fp32 accumulate everywhere. Measured rel err ~3.8e-4.
// R7: fragment loads hoisted out of the combo loop (LDSM -33% in NA=2 path).
// ---------------------------------------------------------------------------

#define BATCH 4
#define SEQ   2048
#define DIM   1024
#define MTOT  (BATCH * SEQ)   // 8192

#define AL __align__(128)
__device__ AL __half g_xp0[(size_t)MTOT * DIM];
__device__ AL __half g_xp1[(size_t)MTOT * DIM];
__device__ AL __half g_wqt0[(size_t)DIM * DIM];
__device__ AL __half g_wqt1[(size_t)DIM * DIM];
__device__ AL __half g_wkt0[(size_t)DIM * DIM];
__device__ AL __half g_wkt1[(size_t)DIM * DIM];
__device__ AL __half g_wvt0[(size_t)DIM * DIM];
__device__ AL __half g_qp0[(size_t)MTOT * DIM];
__device__ AL __half g_qp1[(size_t)MTOT * DIM];
__device__ AL __half g_kp0[(size_t)MTOT * DIM];
__device__ AL __half g_kp1[(size_t)MTOT * DIM];
__device__ AL __half g_vp[(size_t)MTOT * DIM];
__device__ AL __half g_vt[(size_t)BATCH * DIM * SEQ];
__device__ AL float  g_S[(size_t)BATCH * SEQ * SEQ];
__device__ AL __half g_pp[(size_t)BATCH * SEQ * SEQ];

// ---------------- PTX helpers ------------------------------------------------
__device__ __forceinline__ uint32_t smem_to_u32(const void* p) {
    uint32_t a;
    asm("{ .reg .u64 t; cvta.to.shared.u64 t, %1; cvt.u32.u64 %0, t; }"
        : "=r"(a) : "l"(p));
    return a;
}
#define CP_ASYNC_16(dst, src) \
    asm volatile("cp.async.cg.shared.global [%0], [%1], 16;" \
                 :: "r"(dst), "l"(src) : "memory")
#define CP_COMMIT() asm volatile("cp.async.commit_group;" ::: "memory")
#define CP_WAIT_1() asm volatile("cp.async.wait_group 1;" ::: "memory")

#define LDSM4(r0, r1, r2, r3, addr) \
    asm volatile("ldmatrix.sync.aligned.m8n8.x4.shared.b16 {%0,%1,%2,%3}, [%4];" \
                 : "=r"(r0), "=r"(r1), "=r"(r2), "=r"(r3) : "r"(addr))

#define MMA16816(d, a, b0r, b1r) \
    asm volatile("mma.sync.aligned.m16n8k16.row.col.f32.f16.f16.f32 " \
                 "{%0,%1,%2,%3}, {%4,%5,%6,%7}, {%8,%9}, {%0,%1,%2,%3};" \
                 : "+f"((d)[0]), "+f"((d)[1]), "+f"((d)[2]), "+f"((d)[3]) \
                 : "r"((a)[0]), "r"((a)[1]), "r"((a)[2]), "r"((a)[3]), \
                   "r"(b0r), "r"(b1r))

// ---------------- split helpers ----------------------------------------------
__device__ __forceinline__ uint32_t packh2(__half a, __half b) {
    return (uint32_t)__half_as_ushort(a) | ((uint32_t)__half_as_ushort(b) << 16);
}
__device__ __forceinline__ void split2h(float v, __half& h0, __half& h1) {
    h0 = __float2half_rn(v);
    h1 = __float2half_rn(v - __half2float(h0));
}

// ---------------- GEMM: C[M,N] = sum_cb A_part[CIA] * B_part[CIB]^T -----------
// A parts: M x K row-major (K-major). B parts: N x K row-major (K-major).
// CTA tile 128x128, BK=32, 4 warps (2 M x 2 N), warp tile 64x64.
// 3-stage cp.async ring, one __syncthreads per chunk, 2 CTAs/SM.
// Fragments for ALL parts loaded once per k16; combos reuse them.
// NA: parts per operand (1 or 2). NCOMBO: 1 or 3 ({00,01,10}).
// EPI: 0 = fp32 -> cf;  2 = 2-split fp16 -> c0,c1;  3 = single fp16 -> c0.
template <int NA, int NCOMBO, int EPI>
__global__ void __launch_bounds__(128, 2)
gemm_mma(const __half* __restrict__ a0, const __half* __restrict__ a1,
         const __half* __restrict__ b0, const __half* __restrict__ b1,
         float* __restrict__ cf,
         __half* __restrict__ c0, __half* __restrict__ c1,
         int Ktot, int ldC, size_t strideA, size_t strideB, size_t strideC)
{
    constexpr int CIA[3] = {0, 0, 1};
    constexpr int CIB[3] = {0, 1, 0};
    constexpr uint32_t A_SZ = 8192u;            // 128 x 32 fp16
    constexpr uint32_t B_SZ = 8192u;            // 128 x 32 fp16
    constexpr uint32_t B_OFF = NA * A_SZ;
    constexpr uint32_t STG = NA * (A_SZ + B_SZ);

    extern __shared__ char dsm[];
    const uint32_t sbase = smem_to_u32(dsm);

    const int tid  = threadIdx.x;
    const int wid  = tid >> 5;
    const int lane = tid & 31;
    const int lrow = lane & 15;
    const int lch  = lane >> 4;

    const int wm = (wid & 1) * 64;    // warp M offset
    const int wn = (wid >> 1) * 64;   // warp N offset

    const int mBase = blockIdx.y * 128;
    const int nBase = blockIdx.x * 128;

    const size_t zA = (size_t)blockIdx.z * strideA;
    const size_t zB = (size_t)blockIdx.z * strideB;
    const size_t zC = (size_t)blockIdx.z * strideC;
    const __half* ap[2] = { a0 + zA, (NA == 2) ? a1 + zA : a0 + zA };
    const __half* bp[2] = { b0 + zB, (NA == 2) ? b1 + zB : b0 + zB };

    const int arsw = ((wm + lrow) >> 1) & 3;
    const int brsw = ((wn + lrow) >> 1) & 3;
    const uint32_t aoff = (uint32_t)(wm + lrow) * 64;
    const uint32_t boff = (uint32_t)(wn + lrow) * 64;

    float acc[4][8][4];
#pragma unroll
    for (int i = 0; i < 4; i++)
#pragma unroll
        for (int j = 0; j < 8; j++)
#pragma unroll
            for (int e = 0; e < 4; e++) acc[i][j][e] = 0.0f;

    const int NCHUNK = Ktot >> 5;

    auto load_stage = [&](int chunk, int buf) {
        const int k0 = chunk << 5;
        const uint32_t sb = sbase + (uint32_t)buf * STG;
#pragma unroll
        for (int t = 0; t < NA; ++t) {
            const uint32_t tb = sb + (uint32_t)t * A_SZ;
#pragma unroll
            for (int i = 0; i < 4; ++i) {
                const int id  = tid + i * 128;      // 0..511
                const int row = id >> 2;
                const int c   = id & 3;
                const __half* g = ap[t] + (size_t)(mBase + row) * Ktot + k0 + c * 8;
                const uint32_t d = tb + (uint32_t)row * 64u +
                                   (uint32_t)((c ^ ((row >> 1) & 3)) * 16);
                CP_ASYNC_16(d, g);
            }
        }
#pragma unroll
        for (int t = 0; t < NA; ++t) {
            const uint32_t tb = sb + B_OFF + (uint32_t)t * B_SZ;
#pragma unroll
            for (int i = 0; i < 4; ++i) {
                const int id  = tid + i * 128;      // 0..511
                const int row = id >> 2;
                const int c   = id & 3;
                const __half* g = bp[t] + (size_t)(nBase + row) * Ktot + k0 + c * 8;
                const uint32_t d = tb + (uint32_t)row * 64u +
                                   (uint32_t)((c ^ ((row >> 1) & 3)) * 16);
                CP_ASYNC_16(d, g);
            }
        }
    };

    load_stage(0, 0); CP_COMMIT();
    load_stage(1, 1); CP_COMMIT();

    int buf = 0;
    for (int chunk = 0; chunk < NCHUNK; ++chunk) {
        CP_WAIT_1();
        __syncthreads();

        const uint32_t stb = sbase + (uint32_t)buf * STG;
#pragma unroll
        for (int k16 = 0; k16 < 2; ++k16) {
            const uint32_t asw = (uint32_t)(((k16 * 2 + lch) ^ arsw) * 16);
            const uint32_t bsw = (uint32_t)(((k16 * 2 + lch) ^ brsw) * 16);

            // load fragments for ALL parts once
            uint32_t afr[NA][4][4];
#pragma unroll
            for (int t = 0; t < NA; ++t) {
                const uint32_t abase = stb + (uint32_t)t * A_SZ + aoff + asw;
#pragma unroll
                for (int im = 0; im < 4; ++im)
                    LDSM4(afr[t][im][0], afr[t][im][1], afr[t][im][2], afr[t][im][3],
                          abase + (uint32_t)im * 1024u);
            }
            uint32_t bfr[NA][4][4];
#pragma unroll
            for (int t = 0; t < NA; ++t) {
                const uint32_t bbase = stb + B_OFF + (uint32_t)t * B_SZ + boff + bsw;
#pragma unroll
                for (int g = 0; g < 4; ++g)
                    LDSM4(bfr[t][g][0], bfr[t][g][1], bfr[t][g][2], bfr[t][g][3],
                          bbase + (uint32_t)g * 1024u);
            }

#pragma unroll
            for (int cb = 0; cb < NCOMBO; ++cb) {
                const int ta = CIA[cb] < NA ? CIA[cb] : 0;
                const int tb2 = CIB[cb] < NA ? CIB[cb] : 0;
#pragma unroll
                for (int im = 0; im < 4; ++im)
#pragma unroll
                    for (int in = 0; in < 8; ++in)
                        MMA16816(acc[im][in], afr[ta][im],
                                 bfr[tb2][in >> 1][in & 1],
                                 bfr[tb2][in >> 1][(in & 1) + 2]);
            }
        }
        if (chunk + 2 < NCHUNK) {
            int nb = buf + 2; if (nb >= 3) nb -= 3;
            load_stage(chunk + 2, nb);
        }
        CP_COMMIT();   // keep group counts aligned with wait_group(1)
        if (++buf == 3) buf = 0;
    }

    // ---------------- epilogue ----------------
    const int quad = lane >> 2;       // 0..7
    const int tcol = lane & 3;        // 0..3
#pragma unroll
    for (int im = 0; im < 4; ++im) {
#pragma unroll
        for (int in = 0; in < 8; ++in) {
            const int row = mBase + wm + im * 16 + quad;
            const int col = nBase + wn + in * 8 + tcol * 2;
            const size_t olo = zC + (size_t)row * ldC + col;
            const size_t ohi = zC + (size_t)(row + 8) * ldC + col;
            if constexpr (EPI == 0) {
                *reinterpret_cast<float2*>(cf + olo) =
                    make_float2(acc[im][in][0], acc[im][in][1]);
                *reinterpret_cast<float2*>(cf + ohi) =
                    make_float2(acc[im][in][2], acc[im][in][3]);
            } else if constexpr (EPI == 2) {
                __half xh, xl, yh, yl;
                split2h(acc[im][in][0], xh, xl); split2h(acc[im][in][1], yh, yl);
                *reinterpret_cast<uint32_t*>(c0 + olo) = packh2(xh, yh);
                *reinterpret_cast<uint32_t*>(c1 + olo) = packh2(xl, yl);
                split2h(acc[im][in][2], xh, xl); split2h(acc[im][in][3], yh, yl);
                *reinterpret_cast<uint32_t*>(c0 + ohi) = packh2(xh, yh);
                *reinterpret_cast<uint32_t*>(c1 + ohi) = packh2(xl, yl);
            } else {
                __half2 lo = __floats2half2_rn(acc[im][in][0], acc[im][in][1]);
                __half2 hi = __floats2half2_rn(acc[im][in][2], acc[im][in][3]);
                *reinterpret_cast<__half2*>(c0 + olo) = lo;
                *reinterpret_cast<__half2*>(c0 + ohi) = hi;
            }
        }
    }
}

// ---------------- aux kernels --------------------------------------------------
__global__ void __launch_bounds__(256)
split2_kernel(const float* __restrict__ src, __half* __restrict__ d0,
              __half* __restrict__ d1)
{
    const size_t i = (size_t)blockIdx.x * 256 + threadIdx.x;
    const float4 v = reinterpret_cast<const float4*>(src)[i];
    __half a0, a1, b0, b1, c0, c1, e0, e1;
    split2h(v.x, a0, a1); split2h(v.y, b0, b1);
    split2h(v.z, c0, c1); split2h(v.w, e0, e1);
    reinterpret_cast<uint2*>(d0)[i] = make_uint2(packh2(a0, b0), packh2(c0, e0));
    reinterpret_cast<uint2*>(d1)[i] = make_uint2(packh2(a1, b1), packh2(c1, e1));
}

// W [K,N] fp32 -> transposed 2-way split Wt parts [N,K] fp16
__global__ void __launch_bounds__(256)
wsplit_kernel(const float* __restrict__ W, __half* __restrict__ t0,
              __half* __restrict__ t1)
{
    __shared__ float tile[32][33];
    const int tx = threadIdx.x, ty = threadIdx.y;
    const int k0 = blockIdx.y * 32, n0 = blockIdx.x * 32;
#pragma unroll
    for (int i = 0; i < 4; ++i)
        tile[ty + i * 8][tx] = W[(size_t)(k0 + ty + i * 8) * DIM + n0 + tx];
    __syncthreads();
#pragma unroll
    for (int i = 0; i < 4; ++i) {
        const int n = n0 + ty + i * 8;
        const float v = tile[tx][ty + i * 8];
        __half h0, h1;
        split2h(v, h0, h1);
        t0[(size_t)n * DIM + k0 + tx] = h0;
        if (t1) t1[(size_t)n * DIM + k0 + tx] = h1;
    }
}

// V [B*S, D] fp16 -> Vt [B][D][S] fp16
__global__ void __launch_bounds__(256)
vtrans_kernel(const __half* __restrict__ v, __half* __restrict__ t)
{
    __shared__ __half tile[32][33];
    const int b = blockIdx.z;
    const int tx = threadIdx.x, ty = threadIdx.y;
    const int s0 = blockIdx.x * 32, d0 = blockIdx.y * 32;
#pragma unroll
    for (int i = 0; i < 4; ++i)
        tile[ty + i * 8][tx] = v[((size_t)b * SEQ + s0 + ty + i * 8) * DIM + d0 + tx];
    __syncthreads();
#pragma unroll
    for (int i = 0; i < 4; ++i)
        t[(size_t)b * DIM * SEQ + (size_t)(d0 + ty + i * 8) * SEQ + s0 + tx] =
            tile[tx][ty + i * 8];
}

// row softmax of S (fp32, row length SEQ) -> single fp16 P
__global__ void __launch_bounds__(256)
softmax_kernel(const float* __restrict__ S, __half* __restrict__ p0)
{
    const float4* row = reinterpret_cast<const float4*>(S + (size_t)blockIdx.x * SEQ);
    const int tid = threadIdx.x;

    float4 a = row[tid];
    float4 b = row[tid + 256];

    float m = fmaxf(fmaxf(fmaxf(a.x, a.y), fmaxf(a.z, a.w)),
                    fmaxf(fmaxf(b.x, b.y), fmaxf(b.z, b.w)));
#pragma unroll
    for (int o = 16; o > 0; o >>= 1) m = fmaxf(m, __shfl_xor_sync(0xffffffffu, m, o));

    __shared__ float redmax[8];
    __shared__ float redsum[8];
    if ((tid & 31) == 0) redmax[tid >> 5] = m;
    __syncthreads();
    float mrow = redmax[0];
#pragma unroll
    for (int i = 1; i < 8; ++i) mrow = fmaxf(mrow, redmax[i]);

    a.x = __expf(a.x - mrow); a.y = __expf(a.y - mrow);
    a.z = __expf(a.z - mrow); a.w = __expf(a.w - mrow);
    b.x = __expf(b.x - mrow); b.y = __expf(b.y - mrow);
    b.z = __expf(b.z - mrow); b.w = __expf(b.w - mrow);

    float s = (a.x + a.y) + (a.z + a.w) + (b.x + b.y) + (b.z + b.w);
#pragma unroll
    for (int o = 16; o > 0; o >>= 1) s += __shfl_xor_sync(0xffffffffu, s, o);
    if ((tid & 31) == 0) redsum[tid >> 5] = s;
    __syncthreads();
    float srow = 0.0f;
#pragma unroll
    for (int i = 0; i < 8; ++i) srow += redsum[i];
    const float inv = 1.0f / srow;

    uint2* r0 = reinterpret_cast<uint2*>(p0 + (size_t)blockIdx.x * SEQ);
    r0[tid] = make_uint2(
        packh2(__float2half_rn(a.x * inv), __float2half_rn(a.y * inv)),
        packh2(__float2half_rn(a.z * inv), __float2half_rn(a.w * inv)));
    r0[tid + 256] = make_uint2(
        packh2(__float2half_rn(b.x * inv), __float2half_rn(b.y * inv)),
        packh2(__float2half_rn(b.z * inv), __float2half_rn(b.w * inv)));
}

// ---------------- launch --------------------------------------------------------
extern "C" void kernel_launch(void* const* d_in, const int* in_sizes, int n_in,
                              void* d_out, int out_size)
{
    const float* x  = (const float*)d_in[0];
    const float* Wq = (const float*)d_in[1];
    const float* Wk = (const float*)d_in[2];
    const float* Wv = (const float*)d_in[3];
    float* out = (float*)d_out;

    __half *xp0, *xp1, *wqt0, *wqt1, *wkt0, *wkt1, *wvt0;
    __half *qp0, *qp1, *kp0, *kp1, *vp, *vt, *pp;
    float* S;
    cudaGetSymbolAddress((void**)&xp0, g_xp0);   cudaGetSymbolAddress((void**)&xp1, g_xp1);
    cudaGetSymbolAddress((void**)&wqt0, g_wqt0); cudaGetSymbolAddress((void**)&wqt1, g_wqt1);
    cudaGetSymbolAddress((void**)&wkt0, g_wkt0); cudaGetSymbolAddress((void**)&wkt1, g_wkt1);
    cudaGetSymbolAddress((void**)&wvt0, g_wvt0);
    cudaGetSymbolAddress((void**)&qp0, g_qp0);   cudaGetSymbolAddress((void**)&qp1, g_qp1);
    cudaGetSymbolAddress((void**)&kp0, g_kp0);   cudaGetSymbolAddress((void**)&kp1, g_kp1);
    cudaGetSymbolAddress((void**)&vp, g_vp);     cudaGetSymbolAddress((void**)&vt, g_vt);
    cudaGetSymbolAddress((void**)&pp, g_pp);
    cudaGetSymbolAddress((void**)&S, g_S);

    const int SMEM2 = 3 * 32768;  // NA=2: 3 stages x 32KB = 98304 (2 CTAs/SM)
    const int SMEM1 = 3 * 16384;  // NA=1: 3 stages x 16KB = 49152
    cudaFuncSetAttribute(gemm_mma<2, 3, 2>, cudaFuncAttributeMaxDynamicSharedMemorySize, SMEM2);
    cudaFuncSetAttribute(gemm_mma<2, 3, 0>, cudaFuncAttributeMaxDynamicSharedMemorySize, SMEM2);
    cudaFuncSetAttribute(gemm_mma<1, 1, 3>, cudaFuncAttributeMaxDynamicSharedMemorySize, SMEM1);
    cudaFuncSetAttribute(gemm_mma<1, 1, 0>, cudaFuncAttributeMaxDynamicSharedMemorySize, SMEM1);

    // 1) operand splits
    split2_kernel<<<(MTOT * DIM) / 1024, 256>>>(x, xp0, xp1);
    {
        dim3 g(DIM / 32, DIM / 32), blk(32, 8);
        wsplit_kernel<<<g, blk>>>(Wq, wqt0, wqt1);
        wsplit_kernel<<<g, blk>>>(Wk, wkt0, wkt1);
        wsplit_kernel<<<g, blk>>>(Wv, wvt0, nullptr);
    }

    // 2) projections
    {
        dim3 g(DIM / 128, MTOT / 128, 1);
        gemm_mma<2, 3, 2><<<g, 128, SMEM2>>>(xp0, xp1, wqt0, wqt1,
                                             nullptr, qp0, qp1, DIM, DIM, 0, 0, 0);
        gemm_mma<2, 3, 2><<<g, 128, SMEM2>>>(xp0, xp1, wkt0, wkt1,
                                             nullptr, kp0, kp1, DIM, DIM, 0, 0, 0);
        gemm_mma<1, 1, 3><<<g, 128, SMEM1>>>(xp0, nullptr, wvt0, nullptr,
                                             nullptr, vp, nullptr, DIM, DIM, 0, 0, 0);
    }

    // 3) V transpose (per batch)
    {
        dim3 g(SEQ / 32, DIM / 32, BATCH), blk(32, 8);
        vtrans_kernel<<<g, blk>>>(vp, vt);
    }

    // 4) scores S[b] = Q[b] @ K[b]^T, 3 combos, fp32 out
    {
        dim3 g(SEQ / 128, SEQ / 128, BATCH);
        gemm_mma<2, 3, 0><<<g, 128, SMEM2>>>(qp0, qp1, kp0, kp1,
                                             S, nullptr, nullptr,
                                             DIM, SEQ,
                                             (size_t)SEQ * DIM, (size_t)SEQ * DIM,
                                             (size_t)SEQ * SEQ);
    }

    // 5) softmax -> P (single fp16)
    softmax_kernel<<<BATCH * SEQ, 256>>>(S, pp);

    // 6) O[b] = P[b] @ Vt[b]^T, 1 combo, fp32 out
    {
        dim3 g(DIM / 128, SEQ / 128, BATCH);
        gemm_mma<1, 1, 0><<<g, 128, SMEM1>>>(pp, nullptr, vt, nullptr,
                                             out, nullptr, nullptr,
                                             SEQ, DIM,
                                             (size_t)SEQ * SEQ, (size_t)DIM * SEQ,
                                             (size_t)SEQ * DIM);
    }
}

// round 8
// speedup vs baseline: 3.9898x; 1.1495x over previous
#include <cuda_runtime.h>
#include <cuda_fp16.h>
#include <cstdint>

// ---------------------------------------------------------------------------
// SelfAttention B=4, S=2048, D=1024 fp32.
// mma.sync.m16n8k16 fp16 + ldmatrix + cp.async 3-stage pipeline.
// R8 restructure: S = QK^T = x (Wq Wk^T) x^T.
//   Mt = Wk·Wq^T  (1024x1024, 2-split, 3 combos, stored x32 scale)
//   y  = x·Mt^T   (2-split, 3 combos, epilogue x(1/32))
//   S  = y·x^T    (3 combos)  -> softmax -> fp16 P
//   V  = x·Wv     (single fp16, 1 combo); O = P·V (1 combo)
// fp32 accumulate everywhere. Expected rel err ~3.8e-4 (P/V fp16-dominated).
// ---------------------------------------------------------------------------

#define BATCH 4
#define SEQ   2048
#define DIM   1024
#define MTOT  (BATCH * SEQ)   // 8192

#define AL __align__(128)
__device__ AL __half g_xp0[(size_t)MTOT * DIM];
__device__ AL __half g_xp1[(size_t)MTOT * DIM];
__device__ AL __half g_wq0[(size_t)DIM * DIM];   // Wq row-major splits
__device__ AL __half g_wq1[(size_t)DIM * DIM];
__device__ AL __half g_wk0[(size_t)DIM * DIM];   // Wk row-major splits
__device__ AL __half g_wk1[(size_t)DIM * DIM];
__device__ AL __half g_wvt0[(size_t)DIM * DIM];  // Wv^T single fp16
__device__ AL __half g_mt0[(size_t)DIM * DIM];   // Mt = 32*(Wk Wq^T) splits
__device__ AL __half g_mt1[(size_t)DIM * DIM];
__device__ AL __half g_yp0[(size_t)MTOT * DIM];  // y = x Mt^T / 32 splits
__device__ AL __half g_yp1[(size_t)MTOT * DIM];
__device__ AL __half g_vp[(size_t)MTOT * DIM];
__device__ AL __half g_vt[(size_t)BATCH * DIM * SEQ];
__device__ AL float  g_S[(size_t)BATCH * SEQ * SEQ];
__device__ AL __half g_pp[(size_t)BATCH * SEQ * SEQ];

// ---------------- PTX helpers ------------------------------------------------
__device__ __forceinline__ uint32_t smem_to_u32(const void* p) {
    uint32_t a;
    asm("{ .reg .u64 t; cvta.to.shared.u64 t, %1; cvt.u32.u64 %0, t; }"
        : "=r"(a) : "l"(p));
    return a;
}
#define CP_ASYNC_16(dst, src) \
    asm volatile("cp.async.cg.shared.global [%0], [%1], 16;" \
                 :: "r"(dst), "l"(src) : "memory")
#define CP_COMMIT() asm volatile("cp.async.commit_group;" ::: "memory")
#define CP_WAIT_1() asm volatile("cp.async.wait_group 1;" ::: "memory")

#define LDSM4(r0, r1, r2, r3, addr) \
    asm volatile("ldmatrix.sync.aligned.m8n8.x4.shared.b16 {%0,%1,%2,%3}, [%4];" \
                 : "=r"(r0), "=r"(r1), "=r"(r2), "=r"(r3) : "r"(addr))

#define MMA16816(d, a, b0r, b1r) \
    asm volatile("mma.sync.aligned.m16n8k16.row.col.f32.f16.f16.f32 " \
                 "{%0,%1,%2,%3}, {%4,%5,%6,%7}, {%8,%9}, {%0,%1,%2,%3};" \
                 : "+f"((d)[0]), "+f"((d)[1]), "+f"((d)[2]), "+f"((d)[3]) \
                 : "r"((a)[0]), "r"((a)[1]), "r"((a)[2]), "r"((a)[3]), \
                   "r"(b0r), "r"(b1r))

// ---------------- split helpers ----------------------------------------------
__device__ __forceinline__ uint32_t packh2(__half a, __half b) {
    return (uint32_t)__half_as_ushort(a) | ((uint32_t)__half_as_ushort(b) << 16);
}
__device__ __forceinline__ void split2h(float v, __half& h0, __half& h1) {
    h0 = __float2half_rn(v);
    h1 = __float2half_rn(v - __half2float(h0));
}

// ---------------- GEMM: C[M,N] = cscale * sum_cb A[CIA] * B[CIB]^T ------------
// A parts: M x K row-major (K-major). B parts: N x K row-major (K-major).
// CTA tile 128x128, BK=32, 4 warps (2 M x 2 N), warp tile 64x64.
// 3-stage cp.async ring, one __syncthreads per chunk, 2 CTAs/SM.
// NA: parts per operand (1 or 2). NCOMBO: 1 or 3 ({00,01,10}).
// EPI: 0 = fp32 -> cf;  2 = 2-split fp16 -> c0,c1;  3 = single fp16 -> c0.
template <int NA, int NCOMBO, int EPI>
__global__ void __launch_bounds__(128, 2)
gemm_mma(const __half* __restrict__ a0, const __half* __restrict__ a1,
         const __half* __restrict__ b0, const __half* __restrict__ b1,
         float* __restrict__ cf,
         __half* __restrict__ c0, __half* __restrict__ c1,
         int Ktot, int ldC, size_t strideA, size_t strideB, size_t strideC,
         float cscale)
{
    constexpr int CIA[3] = {0, 0, 1};
    constexpr int CIB[3] = {0, 1, 0};
    constexpr uint32_t A_SZ = 8192u;            // 128 x 32 fp16
    constexpr uint32_t B_SZ = 8192u;            // 128 x 32 fp16
    constexpr uint32_t B_OFF = NA * A_SZ;
    constexpr uint32_t STG = NA * (A_SZ + B_SZ);

    extern __shared__ char dsm[];
    const uint32_t sbase = smem_to_u32(dsm);

    const int tid  = threadIdx.x;
    const int wid  = tid >> 5;
    const int lane = tid & 31;
    const int lrow = lane & 15;
    const int lch  = lane >> 4;

    const int wm = (wid & 1) * 64;    // warp M offset
    const int wn = (wid >> 1) * 64;   // warp N offset

    const int mBase = blockIdx.y * 128;
    const int nBase = blockIdx.x * 128;

    const size_t zA = (size_t)blockIdx.z * strideA;
    const size_t zB = (size_t)blockIdx.z * strideB;
    const size_t zC = (size_t)blockIdx.z * strideC;
    const __half* ap[2] = { a0 + zA, (NA == 2) ? a1 + zA : a0 + zA };
    const __half* bp[2] = { b0 + zB, (NA == 2) ? b1 + zB : b0 + zB };

    const int arsw = ((wm + lrow) >> 1) & 3;
    const int brsw = ((wn + lrow) >> 1) & 3;
    const uint32_t aoff = (uint32_t)(wm + lrow) * 64;
    const uint32_t boff = (uint32_t)(wn + lrow) * 64;

    float acc[4][8][4];
#pragma unroll
    for (int i = 0; i < 4; i++)
#pragma unroll
        for (int j = 0; j < 8; j++)
#pragma unroll
            for (int e = 0; e < 4; e++) acc[i][j][e] = 0.0f;

    const int NCHUNK = Ktot >> 5;

    auto load_stage = [&](int chunk, int buf) {
        const int k0 = chunk << 5;
        const uint32_t sb = sbase + (uint32_t)buf * STG;
#pragma unroll
        for (int t = 0; t < NA; ++t) {
            const uint32_t tb = sb + (uint32_t)t * A_SZ;
#pragma unroll
            for (int i = 0; i < 4; ++i) {
                const int id  = tid + i * 128;      // 0..511
                const int row = id >> 2;
                const int c   = id & 3;
                const __half* g = ap[t] + (size_t)(mBase + row) * Ktot + k0 + c * 8;
                const uint32_t d = tb + (uint32_t)row * 64u +
                                   (uint32_t)((c ^ ((row >> 1) & 3)) * 16);
                CP_ASYNC_16(d, g);
            }
        }
#pragma unroll
        for (int t = 0; t < NA; ++t) {
            const uint32_t tb = sb + B_OFF + (uint32_t)t * B_SZ;
#pragma unroll
            for (int i = 0; i < 4; ++i) {
                const int id  = tid + i * 128;      // 0..511
                const int row = id >> 2;
                const int c   = id & 3;
                const __half* g = bp[t] + (size_t)(nBase + row) * Ktot + k0 + c * 8;
                const uint32_t d = tb + (uint32_t)row * 64u +
                                   (uint32_t)((c ^ ((row >> 1) & 3)) * 16);
                CP_ASYNC_16(d, g);
            }
        }
    };

    load_stage(0, 0); CP_COMMIT();
    load_stage(1, 1); CP_COMMIT();

    int buf = 0;
    for (int chunk = 0; chunk < NCHUNK; ++chunk) {
        CP_WAIT_1();
        __syncthreads();

        const uint32_t stb = sbase + (uint32_t)buf * STG;
#pragma unroll
        for (int k16 = 0; k16 < 2; ++k16) {
            const uint32_t asw = (uint32_t)(((k16 * 2 + lch) ^ arsw) * 16);
            const uint32_t bsw = (uint32_t)(((k16 * 2 + lch) ^ brsw) * 16);

            // load fragments for ALL parts once; combos reuse them
            uint32_t afr[NA][4][4];
#pragma unroll
            for (int t = 0; t < NA; ++t) {
                const uint32_t abase = stb + (uint32_t)t * A_SZ + aoff + asw;
#pragma unroll
                for (int im = 0; im < 4; ++im)
                    LDSM4(afr[t][im][0], afr[t][im][1], afr[t][im][2], afr[t][im][3],
                          abase + (uint32_t)im * 1024u);
            }
            uint32_t bfr[NA][4][4];
#pragma unroll
            for (int t = 0; t < NA; ++t) {
                const uint32_t bbase = stb + B_OFF + (uint32_t)t * B_SZ + boff + bsw;
#pragma unroll
                for (int g = 0; g < 4; ++g)
                    LDSM4(bfr[t][g][0], bfr[t][g][1], bfr[t][g][2], bfr[t][g][3],
                          bbase + (uint32_t)g * 1024u);
            }

#pragma unroll
            for (int cb = 0; cb < NCOMBO; ++cb) {
                const int ta = CIA[cb] < NA ? CIA[cb] : 0;
                const int tb2 = CIB[cb] < NA ? CIB[cb] : 0;
#pragma unroll
                for (int im = 0; im < 4; ++im)
#pragma unroll
                    for (int in = 0; in < 8; ++in)
                        MMA16816(acc[im][in], afr[ta][im],
                                 bfr[tb2][in >> 1][in & 1],
                                 bfr[tb2][in >> 1][(in & 1) + 2]);
            }
        }
        if (chunk + 2 < NCHUNK) {
            int nb = buf + 2; if (nb >= 3) nb -= 3;
            load_stage(chunk + 2, nb);
        }
        CP_COMMIT();   // keep group counts aligned with wait_group(1)
        if (++buf == 3) buf = 0;
    }

    // ---------------- epilogue ----------------
    const int quad = lane >> 2;       // 0..7
    const int tcol = lane & 3;        // 0..3
#pragma unroll
    for (int im = 0; im < 4; ++im) {
#pragma unroll
        for (int in = 0; in < 8; ++in) {
            const int row = mBase + wm + im * 16 + quad;
            const int col = nBase + wn + in * 8 + tcol * 2;
            const size_t olo = zC + (size_t)row * ldC + col;
            const size_t ohi = zC + (size_t)(row + 8) * ldC + col;
            const float v0 = acc[im][in][0] * cscale;
            const float v1 = acc[im][in][1] * cscale;
            const float v2 = acc[im][in][2] * cscale;
            const float v3 = acc[im][in][3] * cscale;
            if constexpr (EPI == 0) {
                *reinterpret_cast<float2*>(cf + olo) = make_float2(v0, v1);
                *reinterpret_cast<float2*>(cf + ohi) = make_float2(v2, v3);
            } else if constexpr (EPI == 2) {
                __half xh, xl, yh, yl;
                split2h(v0, xh, xl); split2h(v1, yh, yl);
                *reinterpret_cast<uint32_t*>(c0 + olo) = packh2(xh, yh);
                *reinterpret_cast<uint32_t*>(c1 + olo) = packh2(xl, yl);
                split2h(v2, xh, xl); split2h(v3, yh, yl);
                *reinterpret_cast<uint32_t*>(c0 + ohi) = packh2(xh, yh);
                *reinterpret_cast<uint32_t*>(c1 + ohi) = packh2(xl, yl);
            } else {
                *reinterpret_cast<__half2*>(c0 + olo) = __floats2half2_rn(v0, v1);
                *reinterpret_cast<__half2*>(c0 + ohi) = __floats2half2_rn(v2, v3);
            }
        }
    }
}

// ---------------- aux kernels --------------------------------------------------
// elementwise fp32 -> 2-split fp16 (any contiguous array, n % 1024 == 0)
__global__ void __launch_bounds__(256)
split2_kernel(const float* __restrict__ src, __half* __restrict__ d0,
              __half* __restrict__ d1)
{
    const size_t i = (size_t)blockIdx.x * 256 + threadIdx.x;
    const float4 v = reinterpret_cast<const float4*>(src)[i];
    __half a0, a1, b0, b1, c0, c1, e0, e1;
    split2h(v.x, a0, a1); split2h(v.y, b0, b1);
    split2h(v.z, c0, c1); split2h(v.w, e0, e1);
    reinterpret_cast<uint2*>(d0)[i] = make_uint2(packh2(a0, b0), packh2(c0, e0));
    reinterpret_cast<uint2*>(d1)[i] = make_uint2(packh2(a1, b1), packh2(c1, e1));
}

// W [K,N] fp32 -> transposed single-fp16 Wt [N,K]
__global__ void __launch_bounds__(256)
wsplit_kernel(const float* __restrict__ W, __half* __restrict__ t0)
{
    __shared__ float tile[32][33];
    const int tx = threadIdx.x, ty = threadIdx.y;
    const int k0 = blockIdx.y * 32, n0 = blockIdx.x * 32;
#pragma unroll
    for (int i = 0; i < 4; ++i)
        tile[ty + i * 8][tx] = W[(size_t)(k0 + ty + i * 8) * DIM + n0 + tx];
    __syncthreads();
#pragma unroll
    for (int i = 0; i < 4; ++i) {
        const int n = n0 + ty + i * 8;
        t0[(size_t)n * DIM + k0 + tx] = __float2half_rn(tile[tx][ty + i * 8]);
    }
}

// V [B*S, D] fp16 -> Vt [B][D][S] fp16
__global__ void __launch_bounds__(256)
vtrans_kernel(const __half* __restrict__ v, __half* __restrict__ t)
{
    __shared__ __half tile[32][33];
    const int b = blockIdx.z;
    const int tx = threadIdx.x, ty = threadIdx.y;
    const int s0 = blockIdx.x * 32, d0 = blockIdx.y * 32;
#pragma unroll
    for (int i = 0; i < 4; ++i)
        tile[ty + i * 8][tx] = v[((size_t)b * SEQ + s0 + ty + i * 8) * DIM + d0 + tx];
    __syncthreads();
#pragma unroll
    for (int i = 0; i < 4; ++i)
        t[(size_t)b * DIM * SEQ + (size_t)(d0 + ty + i * 8) * SEQ + s0 + tx] =
            tile[tx][ty + i * 8];
}

// row softmax of S (fp32, row length SEQ) -> single fp16 P
__global__ void __launch_bounds__(256)
softmax_kernel(const float* __restrict__ S, __half* __restrict__ p0)
{
    const float4* row = reinterpret_cast<const float4*>(S + (size_t)blockIdx.x * SEQ);
    const int tid = threadIdx.x;

    float4 a = row[tid];
    float4 b = row[tid + 256];

    float m = fmaxf(fmaxf(fmaxf(a.x, a.y), fmaxf(a.z, a.w)),
                    fmaxf(fmaxf(b.x, b.y), fmaxf(b.z, b.w)));
#pragma unroll
    for (int o = 16; o > 0; o >>= 1) m = fmaxf(m, __shfl_xor_sync(0xffffffffu, m, o));

    __shared__ float redmax[8];
    __shared__ float redsum[8];
    if ((tid & 31) == 0) redmax[tid >> 5] = m;
    __syncthreads();
    float mrow = redmax[0];
#pragma unroll
    for (int i = 1; i < 8; ++i) mrow = fmaxf(mrow, redmax[i]);

    a.x = __expf(a.x - mrow); a.y = __expf(a.y - mrow);
    a.z = __expf(a.z - mrow); a.w = __expf(a.w - mrow);
    b.x = __expf(b.x - mrow); b.y = __expf(b.y - mrow);
    b.z = __expf(b.z - mrow); b.w = __expf(b.w - mrow);

    float s = (a.x + a.y) + (a.z + a.w) + (b.x + b.y) + (b.z + b.w);
#pragma unroll
    for (int o = 16; o > 0; o >>= 1) s += __shfl_xor_sync(0xffffffffu, s, o);
    if ((tid & 31) == 0) redsum[tid >> 5] = s;
    __syncthreads();
    float srow = 0.0f;
#pragma unroll
    for (int i = 0; i < 8; ++i) srow += redsum[i];
    const float inv = 1.0f / srow;

    uint2* r0 = reinterpret_cast<uint2*>(p0 + (size_t)blockIdx.x * SEQ);
    r0[tid] = make_uint2(
        packh2(__float2half_rn(a.x * inv), __float2half_rn(a.y * inv)),
        packh2(__float2half_rn(a.z * inv), __float2half_rn(a.w * inv)));
    r0[tid + 256] = make_uint2(
        packh2(__float2half_rn(b.x * inv), __float2half_rn(b.y * inv)),
        packh2(__float2half_rn(b.z * inv), __float2half_rn(b.w * inv)));
}

// ---------------- launch --------------------------------------------------------
extern "C" void kernel_launch(void* const* d_in, const int* in_sizes, int n_in,
                              void* d_out, int out_size)
{
    const float* x  = (const float*)d_in[0];
    const float* Wq = (const float*)d_in[1];
    const float* Wk = (const float*)d_in[2];
    const float* Wv = (const float*)d_in[3];
    float* out = (float*)d_out;

    __half *xp0, *xp1, *wq0, *wq1, *wk0, *wk1, *wvt0;
    __half *mt0, *mt1, *yp0, *yp1, *vp, *vt, *pp;
    float* S;
    cudaGetSymbolAddress((void**)&xp0, g_xp0);  cudaGetSymbolAddress((void**)&xp1, g_xp1);
    cudaGetSymbolAddress((void**)&wq0, g_wq0);  cudaGetSymbolAddress((void**)&wq1, g_wq1);
    cudaGetSymbolAddress((void**)&wk0, g_wk0);  cudaGetSymbolAddress((void**)&wk1, g_wk1);
    cudaGetSymbolAddress((void**)&wvt0, g_wvt0);
    cudaGetSymbolAddress((void**)&mt0, g_mt0);  cudaGetSymbolAddress((void**)&mt1, g_mt1);
    cudaGetSymbolAddress((void**)&yp0, g_yp0);  cudaGetSymbolAddress((void**)&yp1, g_yp1);
    cudaGetSymbolAddress((void**)&vp, g_vp);    cudaGetSymbolAddress((void**)&vt, g_vt);
    cudaGetSymbolAddress((void**)&pp, g_pp);
    cudaGetSymbolAddress((void**)&S, g_S);

    const int SMEM2 = 3 * 32768;  // NA=2: 3 stages x 32KB (2 CTAs/SM)
    const int SMEM1 = 3 * 16384;  // NA=1
    cudaFuncSetAttribute(gemm_mma<2, 3, 2>, cudaFuncAttributeMaxDynamicSharedMemorySize, SMEM2);
    cudaFuncSetAttribute(gemm_mma<2, 3, 0>, cudaFuncAttributeMaxDynamicSharedMemorySize, SMEM2);
    cudaFuncSetAttribute(gemm_mma<1, 1, 3>, cudaFuncAttributeMaxDynamicSharedMemorySize, SMEM1);
    cudaFuncSetAttribute(gemm_mma<1, 1, 0>, cudaFuncAttributeMaxDynamicSharedMemorySize, SMEM1);

    // 1) operand splits
    split2_kernel<<<(MTOT * DIM) / 1024, 256>>>(x, xp0, xp1);
    split2_kernel<<<(DIM * DIM) / 1024, 256>>>(Wq, wq0, wq1);   // row-major splits
    split2_kernel<<<(DIM * DIM) / 1024, 256>>>(Wk, wk0, wk1);
    {
        dim3 g(DIM / 32, DIM / 32), blk(32, 8);
        wsplit_kernel<<<g, blk>>>(Wv, wvt0);                    // Wv^T single fp16
    }

    // 2) Mt = 32 * (Wk Wq^T)   [d',d],  A=Wk (K-major ✓), B=Wq (K-major ✓)
    {
        dim3 g(DIM / 128, DIM / 128, 1);
        gemm_mma<2, 3, 2><<<g, 128, SMEM2>>>(wk0, wk1, wq0, wq1,
                                             nullptr, mt0, mt1,
                                             DIM, DIM, 0, 0, 0, 32.0f);
    }

    // 3) y = (x Mt^T) / 32  [8192,1024], 2-split out;  V = x Wv (single fp16)
    {
        dim3 g(DIM / 128, MTOT / 128, 1);
        gemm_mma<2, 3, 2><<<g, 128, SMEM2>>>(xp0, xp1, mt0, mt1,
                                             nullptr, yp0, yp1,
                                             DIM, DIM, 0, 0, 0, 1.0f / 32.0f);
        gemm_mma<1, 1, 3><<<g, 128, SMEM1>>>(xp0, nullptr, wvt0, nullptr,
                                             nullptr, vp, nullptr,
                                             DIM, DIM, 0, 0, 0, 1.0f);
    }

    // 4) V transpose (per batch)
    {
        dim3 g(SEQ / 32, DIM / 32, BATCH), blk(32, 8);
        vtrans_kernel<<<g, blk>>>(vp, vt);
    }

    // 5) scores S[b] = y[b] @ x[b]^T, 3 combos, fp32 out
    {
        dim3 g(SEQ / 128, SEQ / 128, BATCH);
        gemm_mma<2, 3, 0><<<g, 128, SMEM2>>>(yp0, yp1, xp0, xp1,
                                             S, nullptr, nullptr,
                                             DIM, SEQ,
                                             (size_t)SEQ * DIM, (size_t)SEQ * DIM,
                                             (size_t)SEQ * SEQ, 1.0f);
    }

    // 6) softmax -> P (single fp16)
    softmax_kernel<<<BATCH * SEQ, 256>>>(S, pp);

    // 7) O[b] = P[b] @ Vt[b]^T, 1 combo, fp32 out
    {
        dim3 g(DIM / 128, SEQ / 128, BATCH);
        gemm_mma<1, 1, 0><<<g, 128, SMEM1>>>(pp, nullptr, vt, nullptr,
                                             out, nullptr, nullptr,
                                             SEQ, DIM,
                                             (size_t)SEQ * SEQ, (size_t)DIM * SEQ,
                                             (size_t)SEQ * DIM, 1.0f);
    }
}